// round 1
// baseline (speedup 1.0000x reference)
#include <cuda_runtime.h>
#include <math.h>

#define B_  4
#define S_  2048
#define D_  768
#define H_  12
#define DH_ 64
#define M_  (B_*S_)          // 8192
#define NROWS_ (B_*H_*S_)    // 98304

// Scratch (allocation-free: static __device__ globals)
__device__ float g_q[B_*H_*S_*DH_];
__device__ float g_k[B_*H_*S_*DH_];
__device__ float g_v[B_*H_*S_*DH_];
__device__ float g_ctx[B_*S_*D_];

// ---------------------------------------------------------------------------
// Tiled fp32 GEMM:  C[M,N] = A[M,K] @ W[N,K]^T + bias[N]
// BM=BN=64, BK=16, 256 threads (16x16), 4x4 register tile per thread.
// split_heads=1: write out[((b*H+h)*S + s)*DH + d]   (m=b*S+s, n=h*DH+d)
// split_heads=0: write out[m*D + n]
// ---------------------------------------------------------------------------
__global__ void gemm_kernel(const float* __restrict__ A,
                            const float* __restrict__ W,
                            const float* __restrict__ bias,
                            float* __restrict__ out,
                            int split_heads)
{
    __shared__ float As[16][68];
    __shared__ float Ws[16][68];

    const int tid = threadIdx.x;
    const int tx  = tid & 15;
    const int ty  = tid >> 4;
    const int m0  = blockIdx.y * 64;
    const int n0  = blockIdx.x * 64;

    float acc[4][4];
#pragma unroll
    for (int i = 0; i < 4; i++)
#pragma unroll
        for (int j = 0; j < 4; j++) acc[i][j] = 0.f;

    const int lr = tid >> 2;        // 0..63
    const int lc = (tid & 3) * 4;   // 0,4,8,12

    for (int k0 = 0; k0 < D_; k0 += 16) {
        float4 va = *reinterpret_cast<const float4*>(&A[(size_t)(m0 + lr) * D_ + k0 + lc]);
        float4 vw = *reinterpret_cast<const float4*>(&W[(size_t)(n0 + lr) * D_ + k0 + lc]);
        As[lc + 0][lr] = va.x; As[lc + 1][lr] = va.y;
        As[lc + 2][lr] = va.z; As[lc + 3][lr] = va.w;
        Ws[lc + 0][lr] = vw.x; Ws[lc + 1][lr] = vw.y;
        Ws[lc + 2][lr] = vw.z; Ws[lc + 3][lr] = vw.w;
        __syncthreads();

#pragma unroll
        for (int kk = 0; kk < 16; kk++) {
            float a[4], b[4];
#pragma unroll
            for (int i = 0; i < 4; i++) a[i] = As[kk][ty * 4 + i];
#pragma unroll
            for (int j = 0; j < 4; j++) b[j] = Ws[kk][tx * 4 + j];
#pragma unroll
            for (int i = 0; i < 4; i++)
#pragma unroll
                for (int j = 0; j < 4; j++) acc[i][j] += a[i] * b[j];
        }
        __syncthreads();
    }

#pragma unroll
    for (int i = 0; i < 4; i++) {
        const int m = m0 + ty * 4 + i;
#pragma unroll
        for (int j = 0; j < 4; j++) {
            const int n = n0 + tx * 4 + j;
            const float val = acc[i][j] + bias[n];
            if (split_heads) {
                const int bb = m >> 11;       // m / S
                const int ss = m & (S_ - 1);  // m % S
                const int hh = n >> 6;        // n / DH
                const int dd = n & 63;        // n % DH
                out[(((size_t)(bb * H_ + hh)) * S_ + ss) * DH_ + dd] = val;
            } else {
                out[(size_t)m * D_ + n] = val;
            }
        }
    }
}

// ---------------------------------------------------------------------------
// In-place L2 normalize rows of 64 (q then k). One warp per row.
// ---------------------------------------------------------------------------
__global__ void l2norm_kernel(float* __restrict__ q, float* __restrict__ k)
{
    const int gw   = (blockIdx.x * blockDim.x + threadIdx.x) >> 5;
    const int lane = threadIdx.x & 31;
    float* p = (gw < NROWS_) ? (q + (size_t)gw * DH_)
                             : (k + (size_t)(gw - NROWS_) * DH_);
    float a  = p[lane];
    float b  = p[lane + 32];
    float ss = a * a + b * b;
#pragma unroll
    for (int off = 16; off >= 1; off >>= 1)
        ss += __shfl_xor_sync(0xffffffffu, ss, off);
    const float inv = 1.f / fmaxf(sqrtf(ss), 1e-12f);
    p[lane]      = a * inv;
    p[lane + 32] = b * inv;
}

// ---------------------------------------------------------------------------
// Flash attention, fp32.  Grid: (S/64, B*H).  256 threads (16x16), 4x4 tiles.
// q,k already L2-normalized.  scale = exp(min(logit_scale[h], ln 100)).
// Writes ctx in [B, S, D] layout (head transpose fused).
// ---------------------------------------------------------------------------
#define ATTN_SMEM (4 * 64 * 68 * 4)

__global__ void attn_kernel(const float* __restrict__ q,
                            const float* __restrict__ k,
                            const float* __restrict__ v,
                            const float* __restrict__ logit_scale,
                            float* __restrict__ ctx)
{
    extern __shared__ float sm[];
    float (*Qs)[68] = reinterpret_cast<float(*)[68]>(sm);              // [r][d]
    float (*Ks)[68] = reinterpret_cast<float(*)[68]>(sm + 64 * 68);    // [d][c]  (transposed)
    float (*Vs)[68] = reinterpret_cast<float(*)[68]>(sm + 2 * 64 * 68);// [c][d]
    float (*Ps)[68] = reinterpret_cast<float(*)[68]>(sm + 3 * 64 * 68);// [r][c]

    const int tid = threadIdx.x;
    const int tx  = tid & 15;
    const int ty  = tid >> 4;
    const int bh  = blockIdx.y;
    const int h   = bh % H_;
    const int b   = bh / H_;
    const int q0  = blockIdx.x * 64;
    const float scale = __expf(fminf(logit_scale[h], 4.6051701859880914f)); // ln(100)
    const size_t base = (size_t)bh * S_ * DH_;

    // Load Q tile (64 x 64)
#pragma unroll
    for (int it = 0; it < 4; it++) {
        const int idx = it * 1024 + tid * 4;
        const int r = idx >> 6, c = idx & 63;
        float4 t = *reinterpret_cast<const float4*>(&q[base + (size_t)(q0 + r) * DH_ + c]);
        *reinterpret_cast<float4*>(&Qs[r][c]) = t;
    }

    float m_i[4], l_i[4], o[4][4];
#pragma unroll
    for (int i = 0; i < 4; i++) {
        m_i[i] = -INFINITY; l_i[i] = 0.f;
#pragma unroll
        for (int j = 0; j < 4; j++) o[i][j] = 0.f;
    }

    for (int k0 = 0; k0 < S_; k0 += 64) {
        __syncthreads();  // previous iteration's PV reads done before overwriting tiles
#pragma unroll
        for (int it = 0; it < 4; it++) {
            const int idx = it * 1024 + tid * 4;
            const int r = idx >> 6, c = idx & 63;
            float4 tk = *reinterpret_cast<const float4*>(&k[base + (size_t)(k0 + r) * DH_ + c]);
            Ks[c + 0][r] = tk.x; Ks[c + 1][r] = tk.y;
            Ks[c + 2][r] = tk.z; Ks[c + 3][r] = tk.w;
            float4 tv = *reinterpret_cast<const float4*>(&v[base + (size_t)(k0 + r) * DH_ + c]);
            *reinterpret_cast<float4*>(&Vs[r][c]) = tv;
        }
        __syncthreads();

        // S = (Q K^T) * scale
        float s[4][4];
#pragma unroll
        for (int i = 0; i < 4; i++)
#pragma unroll
            for (int j = 0; j < 4; j++) s[i][j] = 0.f;

#pragma unroll 8
        for (int d = 0; d < 64; d++) {
            float a[4], kb[4];
#pragma unroll
            for (int i = 0; i < 4; i++) a[i]  = Qs[ty * 4 + i][d];
#pragma unroll
            for (int j = 0; j < 4; j++) kb[j] = Ks[d][tx * 4 + j];
#pragma unroll
            for (int i = 0; i < 4; i++)
#pragma unroll
                for (int j = 0; j < 4; j++) s[i][j] += a[i] * kb[j];
        }
#pragma unroll
        for (int i = 0; i < 4; i++)
#pragma unroll
            for (int j = 0; j < 4; j++) s[i][j] *= scale;

        // Online softmax (per row: reduce over 16 tx lanes)
#pragma unroll
        for (int i = 0; i < 4; i++) {
            float rmax = fmaxf(fmaxf(s[i][0], s[i][1]), fmaxf(s[i][2], s[i][3]));
#pragma unroll
            for (int off = 8; off >= 1; off >>= 1)
                rmax = fmaxf(rmax, __shfl_xor_sync(0xffffffffu, rmax, off));
            const float mn    = fmaxf(m_i[i], rmax);
            const float alpha = __expf(m_i[i] - mn);
            m_i[i]  = mn;
            l_i[i] *= alpha;
#pragma unroll
            for (int j = 0; j < 4; j++) o[i][j] *= alpha;

            float rsum = 0.f;
#pragma unroll
            for (int j = 0; j < 4; j++) {
                s[i][j] = __expf(s[i][j] - mn);
                rsum += s[i][j];
            }
#pragma unroll
            for (int off = 8; off >= 1; off >>= 1)
                rsum += __shfl_xor_sync(0xffffffffu, rsum, off);
            l_i[i] += rsum;
        }

        // Stage P to smem for the PV GEMM
#pragma unroll
        for (int i = 0; i < 4; i++)
#pragma unroll
            for (int j = 0; j < 4; j++) Ps[ty * 4 + i][tx * 4 + j] = s[i][j];
        __syncthreads();

        // O += P @ V
#pragma unroll 8
        for (int c = 0; c < 64; c++) {
            float p[4], vv[4];
#pragma unroll
            for (int i = 0; i < 4; i++) p[i]  = Ps[ty * 4 + i][c];
#pragma unroll
            for (int j = 0; j < 4; j++) vv[j] = Vs[c][tx * 4 + j];
#pragma unroll
            for (int i = 0; i < 4; i++)
#pragma unroll
                for (int j = 0; j < 4; j++) o[i][j] += p[i] * vv[j];
        }
    }

    // Epilogue: divide by l, write ctx[B,S,D] with head transpose fused
#pragma unroll
    for (int i = 0; i < 4; i++) {
        const int r = q0 + ty * 4 + i;
        const float inv_l = 1.f / l_i[i];
#pragma unroll
        for (int j = 0; j < 4; j++) {
            const int d = tx * 4 + j;
            ctx[((size_t)b * S_ + r) * D_ + h * DH_ + d] = o[i][j] * inv_l;
        }
    }
}

// ---------------------------------------------------------------------------
// Launch
// ---------------------------------------------------------------------------
extern "C" void kernel_launch(void* const* d_in, const int* in_sizes, int n_in,
                              void* d_out, int out_size)
{
    const float* x  = (const float*)d_in[0];
    const float* Wq = (const float*)d_in[1];
    const float* bq = (const float*)d_in[2];
    const float* Wk = (const float*)d_in[3];
    const float* bk = (const float*)d_in[4];
    const float* Wv = (const float*)d_in[5];
    const float* bv = (const float*)d_in[6];
    const float* Wo = (const float*)d_in[7];
    const float* bo = (const float*)d_in[8];
    const float* ls = (const float*)d_in[9];
    float* out = (float*)d_out;

    float *qp, *kp, *vp, *cp;
    cudaGetSymbolAddress((void**)&qp, g_q);
    cudaGetSymbolAddress((void**)&kp, g_k);
    cudaGetSymbolAddress((void**)&vp, g_v);
    cudaGetSymbolAddress((void**)&cp, g_ctx);

    const dim3 gg(D_ / 64, M_ / 64);   // (12, 128)

    gemm_kernel<<<gg, 256>>>(x, Wq, bq, qp, 1);
    gemm_kernel<<<gg, 256>>>(x, Wk, bk, kp, 1);
    gemm_kernel<<<gg, 256>>>(x, Wv, bv, vp, 1);

    l2norm_kernel<<<(2 * NROWS_) / 8, 256>>>(qp, kp);

    cudaFuncSetAttribute(attn_kernel, cudaFuncAttributeMaxDynamicSharedMemorySize, ATTN_SMEM);
    attn_kernel<<<dim3(S_ / 64, B_ * H_), 256, ATTN_SMEM>>>(qp, kp, vp, ls, cp);

    gemm_kernel<<<gg, 256>>>(cp, Wo, bo, out, 0);
}

// round 3
// speedup vs baseline: 1.2958x; 1.2958x over previous
#include <cuda_runtime.h>
#include <cuda_bf16.h>
#include <math.h>
#include <cstdint>

#define B_  4
#define S_  2048
#define D_  768
#define H_  12
#define DH_ 64
#define M_  (B_*S_)          // 8192
#define NROWS_ (B_*H_*S_)    // 98304

// Scratch (allocation-free: static __device__ globals)
__device__ float g_q[B_*H_*S_*DH_];
__device__ float g_k[B_*H_*S_*DH_];
__device__ float g_v[B_*H_*S_*DH_];
__device__ float g_ctx[B_*S_*D_];

// ===========================================================================
// Helpers
// ===========================================================================
__device__ __forceinline__ uint32_t smem_u32(const void* p) {
    uint32_t r;
    asm("{ .reg .u64 t; cvta.to.shared.u64 t, %1; cvt.u32.u64 %0, t; }"
        : "=r"(r) : "l"(p));
    return r;
}

__device__ __forceinline__ void ldsm_x4(uint32_t* r, uint32_t addr) {
    asm volatile("ldmatrix.sync.aligned.m8n8.x4.shared.b16 {%0,%1,%2,%3}, [%4];"
                 : "=r"(r[0]), "=r"(r[1]), "=r"(r[2]), "=r"(r[3]) : "r"(addr));
}

// D += A * B  (m16n8k16, row.col, bf16 in, fp32 accum)
__device__ __forceinline__ void mma16816(float* d, const uint32_t* a, const uint32_t* b) {
    asm volatile(
        "mma.sync.aligned.m16n8k16.row.col.f32.bf16.bf16.f32 "
        "{%0,%1,%2,%3}, {%4,%5,%6,%7}, {%8,%9}, {%0,%1,%2,%3};"
        : "+f"(d[0]), "+f"(d[1]), "+f"(d[2]), "+f"(d[3])
        : "r"(a[0]), "r"(a[1]), "r"(a[2]), "r"(a[3]), "r"(b[0]), "r"(b[1]));
}

// Split fp32 -> (hi, lo) bf16 pair packed as one u32 each lane-pair
__device__ __forceinline__ void split2(float x0, float x1, uint32_t& hi, uint32_t& lo) {
    __nv_bfloat16 h0 = __float2bfloat16_rn(x0);
    __nv_bfloat16 h1 = __float2bfloat16_rn(x1);
    __nv_bfloat16 l0 = __float2bfloat16_rn(x0 - __bfloat162float(h0));
    __nv_bfloat16 l1 = __float2bfloat16_rn(x1 - __bfloat162float(h1));
    hi = (uint32_t)__bfloat16_as_ushort(h0) | ((uint32_t)__bfloat16_as_ushort(h1) << 16);
    lo = (uint32_t)__bfloat16_as_ushort(l0) | ((uint32_t)__bfloat16_as_ushort(l1) << 16);
}

// ===========================================================================
// HMMA bf16x3 GEMM:  C[M,N] = A[M,K] @ W[N,K]^T + bias[N]   (fp32-accurate)
// CTA tile 128x128, BK=32, 8 warps (2m x 4n), warp tile 64x32.
// split_heads=1: out[((b*H+h)*S+s)*DH+d]; else out[m*D+n].
// ===========================================================================
#define BK_  32
#define LDA_ 40   // bf16 row stride (32 data + 8 pad) -> conflict-free ldmatrix

__global__ void __launch_bounds__(256)
gemm_mma(const float* __restrict__ A, const float* __restrict__ W,
         const float* __restrict__ bias, float* __restrict__ out, int split_heads)
{
    __shared__ __nv_bfloat16 sAh[128 * LDA_];
    __shared__ __nv_bfloat16 sAl[128 * LDA_];
    __shared__ __nv_bfloat16 sWh[128 * LDA_];
    __shared__ __nv_bfloat16 sWl[128 * LDA_];

    const int tid    = threadIdx.x;
    const int lane   = tid & 31;
    const int wid    = tid >> 5;
    const int warp_m = wid & 1;        // 0..1  (64 rows)
    const int warp_n = wid >> 1;       // 0..3  (32 cols)
    const int m0     = blockIdx.y * 128;
    const int n0     = blockIdx.x * 128;

    float acc[4][4][4];
#pragma unroll
    for (int i = 0; i < 4; i++)
#pragma unroll
        for (int j = 0; j < 4; j++)
#pragma unroll
            for (int e = 0; e < 4; e++) acc[i][j][e] = 0.f;

    // global load mapping: row = tid/2, 16 consecutive floats per thread
    const int grow = tid >> 1;
    const int gcol = (tid & 1) * 16;
    const float* arow = A + (size_t)(m0 + grow) * D_ + gcol;
    const float* wrow = W + (size_t)(n0 + grow) * D_ + gcol;

    // ldmatrix base addresses
    const uint32_t bAh = smem_u32(sAh), bAl = smem_u32(sAl);
    const uint32_t bWh = smem_u32(sWh), bWl = smem_u32(sWl);
    const int r_a = lane & 15, c_a = (lane >> 4) * 8;
    const int r_b = (lane & 7) | ((lane >> 4) << 3);
    const int c_b = ((lane >> 3) & 1) * 8;
    const uint32_t offA = ((warp_m * 64 + r_a) * LDA_ + c_a) * 2;
    const uint32_t offB = ((warp_n * 32 + r_b) * LDA_ + c_b) * 2;

    for (int kc = 0; kc < D_; kc += BK_) {
        // ---- load + split into smem
#pragma unroll
        for (int g = 0; g < 4; g++) {
            float4 va = *reinterpret_cast<const float4*>(arow + kc + g * 4);
            uint32_t h0, l0, h1, l1;
            split2(va.x, va.y, h0, l0);
            split2(va.z, va.w, h1, l1);
            uint32_t* dh = reinterpret_cast<uint32_t*>(&sAh[grow * LDA_ + gcol + g * 4]);
            uint32_t* dl = reinterpret_cast<uint32_t*>(&sAl[grow * LDA_ + gcol + g * 4]);
            dh[0] = h0; dh[1] = h1; dl[0] = l0; dl[1] = l1;

            float4 vw = *reinterpret_cast<const float4*>(wrow + kc + g * 4);
            split2(vw.x, vw.y, h0, l0);
            split2(vw.z, vw.w, h1, l1);
            dh = reinterpret_cast<uint32_t*>(&sWh[grow * LDA_ + gcol + g * 4]);
            dl = reinterpret_cast<uint32_t*>(&sWl[grow * LDA_ + gcol + g * 4]);
            dh[0] = h0; dh[1] = h1; dl[0] = l0; dl[1] = l1;
        }
        __syncthreads();

#pragma unroll
        for (int ks = 0; ks < BK_; ks += 16) {
            const uint32_t ko = ks * 2;
            uint32_t ah[4][4], al[4][4];
#pragma unroll
            for (int mt = 0; mt < 4; mt++) {
                ldsm_x4(ah[mt], bAh + offA + ko + mt * 16 * LDA_ * 2);
                ldsm_x4(al[mt], bAl + offA + ko + mt * 16 * LDA_ * 2);
            }
            uint32_t bh[8], bl[8];
#pragma unroll
            for (int g = 0; g < 2; g++) {
                ldsm_x4(&bh[g * 4], bWh + offB + ko + g * 16 * LDA_ * 2);
                ldsm_x4(&bl[g * 4], bWl + offB + ko + g * 16 * LDA_ * 2);
            }
#pragma unroll
            for (int mt = 0; mt < 4; mt++)
#pragma unroll
                for (int nt = 0; nt < 4; nt++) {
                    mma16816(acc[mt][nt], ah[mt], &bh[nt * 2]);
                    mma16816(acc[mt][nt], ah[mt], &bl[nt * 2]);
                    mma16816(acc[mt][nt], al[mt], &bh[nt * 2]);
                }
        }
        __syncthreads();
    }

    // ---- epilogue: bias add + store (optional head split)
#pragma unroll
    for (int mt = 0; mt < 4; mt++) {
#pragma unroll
        for (int nt = 0; nt < 4; nt++) {
            const int n = n0 + warp_n * 32 + nt * 8 + 2 * (lane & 3);
            const float2 bv = *reinterpret_cast<const float2*>(&bias[n]);
#pragma unroll
            for (int half = 0; half < 2; half++) {
                const int m = m0 + warp_m * 64 + mt * 16 + (lane >> 2) + half * 8;
                float2 o;
                o.x = acc[mt][nt][half * 2 + 0] + bv.x;
                o.y = acc[mt][nt][half * 2 + 1] + bv.y;
                float* dst;
                if (split_heads) {
                    const int bb = m >> 11, ss = m & (S_ - 1);
                    const int hh = n >> 6,  dd = n & 63;
                    dst = out + (((size_t)(bb * H_ + hh)) * S_ + ss) * DH_ + dd;
                } else {
                    dst = out + (size_t)m * D_ + n;
                }
                *reinterpret_cast<float2*>(dst) = o;
            }
        }
    }
}

// ---------------------------------------------------------------------------
// In-place L2 normalize rows of 64 (q then k). One warp per row.
// ---------------------------------------------------------------------------
__global__ void l2norm_kernel(float* __restrict__ q, float* __restrict__ k)
{
    const int gw   = (blockIdx.x * blockDim.x + threadIdx.x) >> 5;
    const int lane = threadIdx.x & 31;
    float* p = (gw < NROWS_) ? (q + (size_t)gw * DH_)
                             : (k + (size_t)(gw - NROWS_) * DH_);
    float a  = p[lane];
    float b  = p[lane + 32];
    float ss = a * a + b * b;
#pragma unroll
    for (int off = 16; off >= 1; off >>= 1)
        ss += __shfl_xor_sync(0xffffffffu, ss, off);
    const float inv = 1.f / fmaxf(sqrtf(ss), 1e-12f);
    p[lane]      = a * inv;
    p[lane + 32] = b * inv;
}

// ---------------------------------------------------------------------------
// Flash attention, fp32.  Grid: (S/64, B*H).  256 threads (16x16), 4x4 tiles.
// ---------------------------------------------------------------------------
#define ATTN_SMEM (4 * 64 * 68 * 4)

__global__ void attn_kernel(const float* __restrict__ q,
                            const float* __restrict__ k,
                            const float* __restrict__ v,
                            const float* __restrict__ logit_scale,
                            float* __restrict__ ctx)
{
    extern __shared__ float sm[];
    float (*Qs)[68] = reinterpret_cast<float(*)[68]>(sm);
    float (*Ks)[68] = reinterpret_cast<float(*)[68]>(sm + 64 * 68);
    float (*Vs)[68] = reinterpret_cast<float(*)[68]>(sm + 2 * 64 * 68);
    float (*Ps)[68] = reinterpret_cast<float(*)[68]>(sm + 3 * 64 * 68);

    const int tid = threadIdx.x;
    const int tx  = tid & 15;
    const int ty  = tid >> 4;
    const int bh  = blockIdx.y;
    const int h   = bh % H_;
    const int b   = bh / H_;
    const int q0  = blockIdx.x * 64;
    const float scale = __expf(fminf(logit_scale[h], 4.6051701859880914f));
    const size_t base = (size_t)bh * S_ * DH_;

#pragma unroll
    for (int it = 0; it < 4; it++) {
        const int idx = it * 1024 + tid * 4;
        const int r = idx >> 6, c = idx & 63;
        float4 t = *reinterpret_cast<const float4*>(&q[base + (size_t)(q0 + r) * DH_ + c]);
        *reinterpret_cast<float4*>(&Qs[r][c]) = t;
    }

    float m_i[4], l_i[4], o[4][4];
#pragma unroll
    for (int i = 0; i < 4; i++) {
        m_i[i] = -INFINITY; l_i[i] = 0.f;
#pragma unroll
        for (int j = 0; j < 4; j++) o[i][j] = 0.f;
    }

    for (int k0 = 0; k0 < S_; k0 += 64) {
        __syncthreads();
#pragma unroll
        for (int it = 0; it < 4; it++) {
            const int idx = it * 1024 + tid * 4;
            const int r = idx >> 6, c = idx & 63;
            float4 tk = *reinterpret_cast<const float4*>(&k[base + (size_t)(k0 + r) * DH_ + c]);
            Ks[c + 0][r] = tk.x; Ks[c + 1][r] = tk.y;
            Ks[c + 2][r] = tk.z; Ks[c + 3][r] = tk.w;
            float4 tv = *reinterpret_cast<const float4*>(&v[base + (size_t)(k0 + r) * DH_ + c]);
            *reinterpret_cast<float4*>(&Vs[r][c]) = tv;
        }
        __syncthreads();

        float s[4][4];
#pragma unroll
        for (int i = 0; i < 4; i++)
#pragma unroll
            for (int j = 0; j < 4; j++) s[i][j] = 0.f;

#pragma unroll 8
        for (int d = 0; d < 64; d++) {
            float a[4], kb[4];
#pragma unroll
            for (int i = 0; i < 4; i++) a[i]  = Qs[ty * 4 + i][d];
#pragma unroll
            for (int j = 0; j < 4; j++) kb[j] = Ks[d][tx * 4 + j];
#pragma unroll
            for (int i = 0; i < 4; i++)
#pragma unroll
                for (int j = 0; j < 4; j++) s[i][j] += a[i] * kb[j];
        }
#pragma unroll
        for (int i = 0; i < 4; i++)
#pragma unroll
            for (int j = 0; j < 4; j++) s[i][j] *= scale;

#pragma unroll
        for (int i = 0; i < 4; i++) {
            float rmax = fmaxf(fmaxf(s[i][0], s[i][1]), fmaxf(s[i][2], s[i][3]));
#pragma unroll
            for (int off = 8; off >= 1; off >>= 1)
                rmax = fmaxf(rmax, __shfl_xor_sync(0xffffffffu, rmax, off));
            const float mn    = fmaxf(m_i[i], rmax);
            const float alpha = __expf(m_i[i] - mn);
            m_i[i]  = mn;
            l_i[i] *= alpha;
#pragma unroll
            for (int j = 0; j < 4; j++) o[i][j] *= alpha;

            float rsum = 0.f;
#pragma unroll
            for (int j = 0; j < 4; j++) {
                s[i][j] = __expf(s[i][j] - mn);
                rsum += s[i][j];
            }
#pragma unroll
            for (int off = 8; off >= 1; off >>= 1)
                rsum += __shfl_xor_sync(0xffffffffu, rsum, off);
            l_i[i] += rsum;
        }

#pragma unroll
        for (int i = 0; i < 4; i++)
#pragma unroll
            for (int j = 0; j < 4; j++) Ps[ty * 4 + i][tx * 4 + j] = s[i][j];
        __syncthreads();

#pragma unroll 8
        for (int c = 0; c < 64; c++) {
            float p[4], vv[4];
#pragma unroll
            for (int i = 0; i < 4; i++) p[i]  = Ps[ty * 4 + i][c];
#pragma unroll
            for (int j = 0; j < 4; j++) vv[j] = Vs[c][tx * 4 + j];
#pragma unroll
            for (int i = 0; i < 4; i++)
#pragma unroll
                for (int j = 0; j < 4; j++) o[i][j] += p[i] * vv[j];
        }
    }

#pragma unroll
    for (int i = 0; i < 4; i++) {
        const int r = q0 + ty * 4 + i;
        const float inv_l = 1.f / l_i[i];
#pragma unroll
        for (int j = 0; j < 4; j++) {
            const int d = tx * 4 + j;
            ctx[((size_t)b * S_ + r) * D_ + h * DH_ + d] = o[i][j] * inv_l;
        }
    }
}

// ---------------------------------------------------------------------------
// Launch
// ---------------------------------------------------------------------------
extern "C" void kernel_launch(void* const* d_in, const int* in_sizes, int n_in,
                              void* d_out, int out_size)
{
    const float* x  = (const float*)d_in[0];
    const float* Wq = (const float*)d_in[1];
    const float* bq = (const float*)d_in[2];
    const float* Wk = (const float*)d_in[3];
    const float* bk = (const float*)d_in[4];
    const float* Wv = (const float*)d_in[5];
    const float* bv = (const float*)d_in[6];
    const float* Wo = (const float*)d_in[7];
    const float* bo = (const float*)d_in[8];
    const float* ls = (const float*)d_in[9];
    float* out = (float*)d_out;

    float *qp, *kp, *vp, *cp;
    cudaGetSymbolAddress((void**)&qp, g_q);
    cudaGetSymbolAddress((void**)&kp, g_k);
    cudaGetSymbolAddress((void**)&vp, g_v);
    cudaGetSymbolAddress((void**)&cp, g_ctx);

    const dim3 gg(D_ / 128, M_ / 128);   // (6, 64)

    gemm_mma<<<gg, 256>>>(x, Wq, bq, qp, 1);
    gemm_mma<<<gg, 256>>>(x, Wk, bk, kp, 1);
    gemm_mma<<<gg, 256>>>(x, Wv, bv, vp, 1);

    l2norm_kernel<<<(2 * NROWS_) / 8, 256>>>(qp, kp);

    cudaFuncSetAttribute(attn_kernel, cudaFuncAttributeMaxDynamicSharedMemorySize, ATTN_SMEM);
    attn_kernel<<<dim3(S_ / 64, B_ * H_), 256, ATTN_SMEM>>>(qp, kp, vp, ls, cp);

    gemm_mma<<<gg, 256>>>(cp, Wo, bo, out, 0);
}

// round 4
// speedup vs baseline: 2.3888x; 1.8435x over previous
#include <cuda_runtime.h>
#include <cuda_bf16.h>
#include <math.h>
#include <cstdint>

#define B_  4
#define S_  2048
#define D_  768
#define H_  12
#define DH_ 64
#define M_  (B_*S_)          // 8192
#define NROWS_ (B_*H_*S_)    // 98304
#define QKVN_ (NROWS_*DH_)   // 6291456

// Scratch (allocation-free: static __device__ globals)
__device__ float g_q[QKVN_];
__device__ float g_k[QKVN_];
__device__ float g_v[QKVN_];
__device__ float g_ctx[M_*D_];
__device__ __nv_bfloat16 g_qh[QKVN_], g_ql[QKVN_];
__device__ __nv_bfloat16 g_kh[QKVN_], g_kl[QKVN_];
__device__ __nv_bfloat16 g_vh[QKVN_], g_vl[QKVN_];

// ===========================================================================
// Helpers
// ===========================================================================
__device__ __forceinline__ uint32_t smem_u32(const void* p) {
    uint32_t r;
    asm("{ .reg .u64 t; cvta.to.shared.u64 t, %1; cvt.u32.u64 %0, t; }"
        : "=r"(r) : "l"(p));
    return r;
}
__device__ __forceinline__ void ldsm_x4(uint32_t* r, uint32_t addr) {
    asm volatile("ldmatrix.sync.aligned.m8n8.x4.shared.b16 {%0,%1,%2,%3}, [%4];"
                 : "=r"(r[0]), "=r"(r[1]), "=r"(r[2]), "=r"(r[3]) : "r"(addr));
}
__device__ __forceinline__ void ldsm_x4_t(uint32_t* r, uint32_t addr) {
    asm volatile("ldmatrix.sync.aligned.m8n8.x4.trans.shared.b16 {%0,%1,%2,%3}, [%4];"
                 : "=r"(r[0]), "=r"(r[1]), "=r"(r[2]), "=r"(r[3]) : "r"(addr));
}
// D += A * B  (m16n8k16, row.col, bf16 in, fp32 accum)
__device__ __forceinline__ void mma16816(float* d, const uint32_t* a,
                                         uint32_t b0, uint32_t b1) {
    asm volatile(
        "mma.sync.aligned.m16n8k16.row.col.f32.bf16.bf16.f32 "
        "{%0,%1,%2,%3}, {%4,%5,%6,%7}, {%8,%9}, {%0,%1,%2,%3};"
        : "+f"(d[0]), "+f"(d[1]), "+f"(d[2]), "+f"(d[3])
        : "r"(a[0]), "r"(a[1]), "r"(a[2]), "r"(a[3]), "r"(b0), "r"(b1));
}
__device__ __forceinline__ void split2(float x0, float x1, uint32_t& hi, uint32_t& lo) {
    __nv_bfloat16 h0 = __float2bfloat16_rn(x0);
    __nv_bfloat16 h1 = __float2bfloat16_rn(x1);
    __nv_bfloat16 l0 = __float2bfloat16_rn(x0 - __bfloat162float(h0));
    __nv_bfloat16 l1 = __float2bfloat16_rn(x1 - __bfloat162float(h1));
    hi = (uint32_t)__bfloat16_as_ushort(h0) | ((uint32_t)__bfloat16_as_ushort(h1) << 16);
    lo = (uint32_t)__bfloat16_as_ushort(l0) | ((uint32_t)__bfloat16_as_ushort(l1) << 16);
}
__device__ __forceinline__ void cp16(uint32_t dst, const void* src) {
    asm volatile("cp.async.cg.shared.global [%0], [%1], 16;" :: "r"(dst), "l"(src));
}
#define CP_COMMIT() asm volatile("cp.async.commit_group;" ::: "memory")
#define CP_WAIT(n)  asm volatile("cp.async.wait_group %0;" :: "n"(n) : "memory")

// ===========================================================================
// HMMA bf16x3 GEMM (unchanged from R3): C[M,N] = A @ W^T + bias
// ===========================================================================
#define BK_  32
#define LDA_ 40

__global__ void __launch_bounds__(256)
gemm_mma(const float* __restrict__ A, const float* __restrict__ W,
         const float* __restrict__ bias, float* __restrict__ out, int split_heads)
{
    __shared__ __nv_bfloat16 sAh[128 * LDA_];
    __shared__ __nv_bfloat16 sAl[128 * LDA_];
    __shared__ __nv_bfloat16 sWh[128 * LDA_];
    __shared__ __nv_bfloat16 sWl[128 * LDA_];

    const int tid    = threadIdx.x;
    const int lane   = tid & 31;
    const int wid    = tid >> 5;
    const int warp_m = wid & 1;
    const int warp_n = wid >> 1;
    const int m0     = blockIdx.y * 128;
    const int n0     = blockIdx.x * 128;

    float acc[4][4][4];
#pragma unroll
    for (int i = 0; i < 4; i++)
#pragma unroll
        for (int j = 0; j < 4; j++)
#pragma unroll
            for (int e = 0; e < 4; e++) acc[i][j][e] = 0.f;

    const int grow = tid >> 1;
    const int gcol = (tid & 1) * 16;
    const float* arow = A + (size_t)(m0 + grow) * D_ + gcol;
    const float* wrow = W + (size_t)(n0 + grow) * D_ + gcol;

    const uint32_t bAh = smem_u32(sAh), bAl = smem_u32(sAl);
    const uint32_t bWh = smem_u32(sWh), bWl = smem_u32(sWl);
    const int r_a = lane & 15, c_a = (lane >> 4) * 8;
    const int r_b = (lane & 7) | ((lane >> 4) << 3);
    const int c_b = ((lane >> 3) & 1) * 8;
    const uint32_t offA = ((warp_m * 64 + r_a) * LDA_ + c_a) * 2;
    const uint32_t offB = ((warp_n * 32 + r_b) * LDA_ + c_b) * 2;

    for (int kc = 0; kc < D_; kc += BK_) {
#pragma unroll
        for (int g = 0; g < 4; g++) {
            float4 va = *reinterpret_cast<const float4*>(arow + kc + g * 4);
            uint32_t h0, l0, h1, l1;
            split2(va.x, va.y, h0, l0);
            split2(va.z, va.w, h1, l1);
            uint32_t* dh = reinterpret_cast<uint32_t*>(&sAh[grow * LDA_ + gcol + g * 4]);
            uint32_t* dl = reinterpret_cast<uint32_t*>(&sAl[grow * LDA_ + gcol + g * 4]);
            dh[0] = h0; dh[1] = h1; dl[0] = l0; dl[1] = l1;

            float4 vw = *reinterpret_cast<const float4*>(wrow + kc + g * 4);
            split2(vw.x, vw.y, h0, l0);
            split2(vw.z, vw.w, h1, l1);
            dh = reinterpret_cast<uint32_t*>(&sWh[grow * LDA_ + gcol + g * 4]);
            dl = reinterpret_cast<uint32_t*>(&sWl[grow * LDA_ + gcol + g * 4]);
            dh[0] = h0; dh[1] = h1; dl[0] = l0; dl[1] = l1;
        }
        __syncthreads();

#pragma unroll
        for (int ks = 0; ks < BK_; ks += 16) {
            const uint32_t ko = ks * 2;
            uint32_t ah[4][4], al[4][4];
#pragma unroll
            for (int mt = 0; mt < 4; mt++) {
                ldsm_x4(ah[mt], bAh + offA + ko + mt * 16 * LDA_ * 2);
                ldsm_x4(al[mt], bAl + offA + ko + mt * 16 * LDA_ * 2);
            }
            uint32_t bh[8], bl[8];
#pragma unroll
            for (int g = 0; g < 2; g++) {
                ldsm_x4(&bh[g * 4], bWh + offB + ko + g * 16 * LDA_ * 2);
                ldsm_x4(&bl[g * 4], bWl + offB + ko + g * 16 * LDA_ * 2);
            }
#pragma unroll
            for (int mt = 0; mt < 4; mt++)
#pragma unroll
                for (int nt = 0; nt < 4; nt++) {
                    mma16816(acc[mt][nt], ah[mt], bh[nt * 2], bh[nt * 2 + 1]);
                    mma16816(acc[mt][nt], ah[mt], bl[nt * 2], bl[nt * 2 + 1]);
                    mma16816(acc[mt][nt], al[mt], bh[nt * 2], bh[nt * 2 + 1]);
                }
        }
        __syncthreads();
    }

#pragma unroll
    for (int mt = 0; mt < 4; mt++) {
#pragma unroll
        for (int nt = 0; nt < 4; nt++) {
            const int n = n0 + warp_n * 32 + nt * 8 + 2 * (lane & 3);
            const float2 bv = *reinterpret_cast<const float2*>(&bias[n]);
#pragma unroll
            for (int half = 0; half < 2; half++) {
                const int m = m0 + warp_m * 64 + mt * 16 + (lane >> 2) + half * 8;
                float2 o;
                o.x = acc[mt][nt][half * 2 + 0] + bv.x;
                o.y = acc[mt][nt][half * 2 + 1] + bv.y;
                float* dst;
                if (split_heads) {
                    const int bb = m >> 11, ss = m & (S_ - 1);
                    const int hh = n >> 6,  dd = n & 63;
                    dst = out + (((size_t)(bb * H_ + hh)) * S_ + ss) * DH_ + dd;
                } else {
                    dst = out + (size_t)m * D_ + n;
                }
                *reinterpret_cast<float2*>(dst) = o;
            }
        }
    }
}

// ===========================================================================
// Prep: normalize q,k (q scaled by per-head exp(min(ls,ln100))), split q,k,v
// into bf16 hi/lo. One warp per row; warps cycle q,k,v.
// ===========================================================================
__global__ void __launch_bounds__(256)
prep_kernel(const float* __restrict__ ls)
{
    const int gw   = (blockIdx.x * blockDim.x + threadIdx.x) >> 5;
    const int lane = threadIdx.x & 31;
    const int tensor = gw / NROWS_;
    const int row    = gw % NROWS_;

    const float* src;
    __nv_bfloat16 *dh, *dl;
    float sc = 1.f;
    bool donorm = true;
    if (tensor == 0) {
        src = g_q; dh = g_qh; dl = g_ql;
        const int hh = (row >> 11) % H_;          // row/(S_) % H
        sc = __expf(fminf(ls[hh], 4.6051701859880914f));
    } else if (tensor == 1) {
        src = g_k; dh = g_kh; dl = g_kl;
    } else {
        src = g_v; dh = g_vh; dl = g_vl; donorm = false;
    }
    const float* p = src + (size_t)row * DH_;
    float a = p[lane];
    float b = p[lane + 32];
    if (donorm) {
        float ss = a * a + b * b;
#pragma unroll
        for (int off = 16; off >= 1; off >>= 1)
            ss += __shfl_xor_sync(0xffffffffu, ss, off);
        const float inv = sc / fmaxf(sqrtf(ss), 1e-12f);
        a *= inv; b *= inv;
    }
    __nv_bfloat16 ah = __float2bfloat16_rn(a);
    __nv_bfloat16 bh = __float2bfloat16_rn(b);
    dh[(size_t)row * DH_ + lane]      = ah;
    dh[(size_t)row * DH_ + lane + 32] = bh;
    dl[(size_t)row * DH_ + lane]      = __float2bfloat16_rn(a - __bfloat162float(ah));
    dl[(size_t)row * DH_ + lane + 32] = __float2bfloat16_rn(b - __bfloat162float(bh));
}

// ===========================================================================
// HMMA flash attention, bf16x3. Grid (S/128, B*H), 256 threads = 8 warps.
// Warp = 16 query rows. KV tile = 64 keys, cp.async double-buffered.
// smem rows padded to 72 bf16 (144B) for conflict-free ldmatrix.
// ===========================================================================
#define ABUF   9216                 // one 64x72 bf16 array
#define ATTN_SMEM (8 * ABUF)        // 2 buffers x {Kh,Kl,Vh,Vl}

__global__ void __launch_bounds__(256)
attn_mma(float* __restrict__ ctx)
{
    extern __shared__ char sm[];
    const uint32_t sbase = smem_u32(sm);
    const int tid  = threadIdx.x;
    const int lane = tid & 31;
    const int wid  = tid >> 5;
    const int bh   = blockIdx.y;
    const int h    = bh % H_;
    const int b    = bh / H_;
    const int q0   = blockIdx.x * 128;
    const size_t base = (size_t)bh * S_ * DH_;

    // ---- stage Q hi/lo (128x64) into smem, build A-fragments, release smem
    {
        const __nv_bfloat16* gq0 = g_qh + base + (size_t)q0 * DH_;
        const __nv_bfloat16* gq1 = g_ql + base + (size_t)q0 * DH_;
#pragma unroll
        for (int i = 0; i < 8; i++) {
            const int arr = i >> 2;
            const int idx = ((i & 3) << 8) + tid;      // 0..1023
            const int row = idx >> 3, c = idx & 7;
            const uint4 v = *reinterpret_cast<const uint4*>(
                (arr ? gq1 : gq0) + row * DH_ + c * 8);
            *reinterpret_cast<uint4*>(sm + arr * 18432 + row * 144 + c * 16) = v;
        }
    }
    __syncthreads();
    uint32_t qfh[4][4], qfl[4][4];
    {
        const uint32_t qa = sbase + (wid * 16 + (lane & 15)) * 144 + (lane >> 4) * 16;
#pragma unroll
        for (int kt = 0; kt < 4; kt++) {
            ldsm_x4(qfh[kt], qa + kt * 32);
            ldsm_x4(qfl[kt], qa + 18432 + kt * 32);
        }
    }
    __syncthreads();

    float o[8][4];
#pragma unroll
    for (int nt = 0; nt < 8; nt++)
#pragma unroll
        for (int e = 0; e < 4; e++) o[nt][e] = 0.f;
    float m0 = -INFINITY, m1 = -INFINITY, l0 = 0.f, l1 = 0.f;

    const uint32_t lofs = (lane & 15) * 144 + (lane >> 4) * 16;

    const __nv_bfloat16* gkh = g_kh + base;
    const __nv_bfloat16* gkl = g_kl + base;
    const __nv_bfloat16* gvh = g_vh + base;
    const __nv_bfloat16* gvl = g_vl + base;

    // issue KV tile 'it' into buffer 'bsel'
    auto issue = [&](int it, int bsel) {
        const int koff = it * 64 * DH_;
#pragma unroll
        for (int i = 0; i < 8; i++) {
            const int arr = i >> 1;
            const int idx = ((i & 1) << 8) + tid;      // 0..511
            const int row = idx >> 3, c = idx & 7;
            const __nv_bfloat16* gp =
                (arr == 0 ? gkh : arr == 1 ? gkl : arr == 2 ? gvh : gvl)
                + koff + row * DH_ + c * 8;
            cp16(sbase + (bsel * 4 + arr) * ABUF + row * 144 + c * 16, gp);
        }
    };

    issue(0, 0);
    CP_COMMIT();

    for (int it = 0; it < S_ / 64; it++) {
        if (it + 1 < S_ / 64) {
            issue(it + 1, (it + 1) & 1);
            CP_COMMIT();
            CP_WAIT(1);
        } else {
            CP_WAIT(0);
        }
        __syncthreads();

        const uint32_t Kh = sbase + (((it & 1) * 4 + 0) * ABUF);
        const uint32_t Kl = Kh + ABUF;
        const uint32_t Vh = Kh + 2 * ABUF;
        const uint32_t Vl = Kh + 3 * ABUF;

        // ---- S = Qs @ K^T (scale pre-folded into q)
        float s[8][4];
#pragma unroll
        for (int nt = 0; nt < 8; nt++)
#pragma unroll
            for (int e = 0; e < 4; e++) s[nt][e] = 0.f;

#pragma unroll
        for (int kt = 0; kt < 4; kt++) {
#pragma unroll
            for (int g = 0; g < 4; g++) {
                uint32_t kf[4], lf[4];
                ldsm_x4(kf, Kh + lofs + g * 16 * 144 + kt * 32);
                ldsm_x4(lf, Kl + lofs + g * 16 * 144 + kt * 32);
                mma16816(s[2 * g],     qfh[kt], kf[0], kf[2]);
                mma16816(s[2 * g],     qfh[kt], lf[0], lf[2]);
                mma16816(s[2 * g],     qfl[kt], kf[0], kf[2]);
                mma16816(s[2 * g + 1], qfh[kt], kf[1], kf[3]);
                mma16816(s[2 * g + 1], qfh[kt], lf[1], lf[3]);
                mma16816(s[2 * g + 1], qfl[kt], kf[1], kf[3]);
            }
        }

        // ---- online softmax (rows: r=lane>>2 and r+8; quad-lane reduce)
        float a0 = -INFINITY, a1 = -INFINITY;
#pragma unroll
        for (int nt = 0; nt < 8; nt++) {
            a0 = fmaxf(a0, fmaxf(s[nt][0], s[nt][1]));
            a1 = fmaxf(a1, fmaxf(s[nt][2], s[nt][3]));
        }
        a0 = fmaxf(a0, __shfl_xor_sync(0xffffffffu, a0, 1));
        a0 = fmaxf(a0, __shfl_xor_sync(0xffffffffu, a0, 2));
        a1 = fmaxf(a1, __shfl_xor_sync(0xffffffffu, a1, 1));
        a1 = fmaxf(a1, __shfl_xor_sync(0xffffffffu, a1, 2));
        const float mn0 = fmaxf(m0, a0);
        const float mn1 = fmaxf(m1, a1);
        const float al0 = __expf(m0 - mn0);
        const float al1 = __expf(m1 - mn1);
        m0 = mn0; m1 = mn1;
        l0 *= al0; l1 *= al1;
#pragma unroll
        for (int nt = 0; nt < 8; nt++) {
            o[nt][0] *= al0; o[nt][1] *= al0;
            o[nt][2] *= al1; o[nt][3] *= al1;
        }
        float sum0 = 0.f, sum1 = 0.f;
#pragma unroll
        for (int nt = 0; nt < 8; nt++) {
            s[nt][0] = __expf(s[nt][0] - mn0);
            s[nt][1] = __expf(s[nt][1] - mn0);
            s[nt][2] = __expf(s[nt][2] - mn1);
            s[nt][3] = __expf(s[nt][3] - mn1);
            sum0 += s[nt][0] + s[nt][1];
            sum1 += s[nt][2] + s[nt][3];
        }
        sum0 += __shfl_xor_sync(0xffffffffu, sum0, 1);
        sum0 += __shfl_xor_sync(0xffffffffu, sum0, 2);
        sum1 += __shfl_xor_sync(0xffffffffu, sum1, 1);
        sum1 += __shfl_xor_sync(0xffffffffu, sum1, 2);
        l0 += sum0; l1 += sum1;

        // ---- O += P @ V  (P from registers; V via ldmatrix.trans)
#pragma unroll
        for (int kt = 0; kt < 4; kt++) {
            uint32_t ah[4], al[4];
            split2(s[2 * kt][0],     s[2 * kt][1],     ah[0], al[0]);
            split2(s[2 * kt][2],     s[2 * kt][3],     ah[1], al[1]);
            split2(s[2 * kt + 1][0], s[2 * kt + 1][1], ah[2], al[2]);
            split2(s[2 * kt + 1][2], s[2 * kt + 1][3], ah[3], al[3]);
#pragma unroll
            for (int g = 0; g < 4; g++) {
                uint32_t vf[4], wf[4];
                ldsm_x4_t(vf, Vh + lofs + kt * 16 * 144 + g * 32);
                ldsm_x4_t(wf, Vl + lofs + kt * 16 * 144 + g * 32);
                mma16816(o[2 * g],     ah, vf[0], vf[1]);
                mma16816(o[2 * g],     ah, wf[0], wf[1]);
                mma16816(o[2 * g],     al, vf[0], vf[1]);
                mma16816(o[2 * g + 1], ah, vf[2], vf[3]);
                mma16816(o[2 * g + 1], ah, wf[2], wf[3]);
                mma16816(o[2 * g + 1], al, vf[2], vf[3]);
            }
        }
        __syncthreads();
    }

    // ---- epilogue
    const float inv0 = 1.f / l0;
    const float inv1 = 1.f / l1;
    const int row0 = q0 + wid * 16 + (lane >> 2);
    const int col0 = h * DH_ + 2 * (lane & 3);
    float* c0 = ctx + ((size_t)b * S_ + row0) * D_ + col0;
    float* c1 = c0 + 8 * D_;
#pragma unroll
    for (int nt = 0; nt < 8; nt++) {
        *reinterpret_cast<float2*>(c0 + nt * 8) =
            make_float2(o[nt][0] * inv0, o[nt][1] * inv0);
        *reinterpret_cast<float2*>(c1 + nt * 8) =
            make_float2(o[nt][2] * inv1, o[nt][3] * inv1);
    }
}

// ---------------------------------------------------------------------------
// Launch
// ---------------------------------------------------------------------------
extern "C" void kernel_launch(void* const* d_in, const int* in_sizes, int n_in,
                              void* d_out, int out_size)
{
    const float* x  = (const float*)d_in[0];
    const float* Wq = (const float*)d_in[1];
    const float* bq = (const float*)d_in[2];
    const float* Wk = (const float*)d_in[3];
    const float* bk = (const float*)d_in[4];
    const float* Wv = (const float*)d_in[5];
    const float* bv = (const float*)d_in[6];
    const float* Wo = (const float*)d_in[7];
    const float* bo = (const float*)d_in[8];
    const float* ls = (const float*)d_in[9];
    float* out = (float*)d_out;

    float *qp, *kp, *vp, *cp;
    cudaGetSymbolAddress((void**)&qp, g_q);
    cudaGetSymbolAddress((void**)&kp, g_k);
    cudaGetSymbolAddress((void**)&vp, g_v);
    cudaGetSymbolAddress((void**)&cp, g_ctx);

    const dim3 gg(D_ / 128, M_ / 128);   // (6, 64)

    gemm_mma<<<gg, 256>>>(x, Wq, bq, qp, 1);
    gemm_mma<<<gg, 256>>>(x, Wk, bk, kp, 1);
    gemm_mma<<<gg, 256>>>(x, Wv, bv, vp, 1);

    prep_kernel<<<(3 * NROWS_) / 8, 256>>>(ls);

    cudaFuncSetAttribute(attn_mma, cudaFuncAttributeMaxDynamicSharedMemorySize, ATTN_SMEM);
    attn_mma<<<dim3(S_ / 128, B_ * H_), 256, ATTN_SMEM>>>(cp);

    gemm_mma<<<gg, 256>>>(cp, Wo, bo, out, 0);
}

// round 5
// speedup vs baseline: 2.9231x; 1.2237x over previous
#include <cuda_runtime.h>
#include <cuda_bf16.h>
#include <math.h>
#include <cstdint>

#define B_  4
#define S_  2048
#define D_  768
#define H_  12
#define DH_ 64
#define M_  (B_*S_)          // 8192
#define NROWS_ (B_*H_*S_)    // 98304
#define QKVN_ (NROWS_*DH_)   // 6291456
#define DD_  (D_*D_)         // 589824

// Scratch (allocation-free: static __device__ globals)
__device__ float g_q[QKVN_];
__device__ float g_k[QKVN_];
__device__ float g_v[QKVN_];
__device__ __nv_bfloat16 g_xh[M_*D_],  g_xl[M_*D_];
__device__ __nv_bfloat16 g_wh[4*DD_],  g_wl[4*DD_];
__device__ __nv_bfloat16 g_qh[QKVN_],  g_ql[QKVN_];
__device__ __nv_bfloat16 g_kh[QKVN_],  g_kl[QKVN_];
__device__ __nv_bfloat16 g_vh[QKVN_],  g_vl[QKVN_];
__device__ __nv_bfloat16 g_ch[M_*D_],  g_cl[M_*D_];

// ===========================================================================
// Helpers
// ===========================================================================
__device__ __forceinline__ uint32_t smem_u32(const void* p) {
    uint32_t r;
    asm("{ .reg .u64 t; cvta.to.shared.u64 t, %1; cvt.u32.u64 %0, t; }"
        : "=r"(r) : "l"(p));
    return r;
}
__device__ __forceinline__ void ldsm_x4(uint32_t* r, uint32_t addr) {
    asm volatile("ldmatrix.sync.aligned.m8n8.x4.shared.b16 {%0,%1,%2,%3}, [%4];"
                 : "=r"(r[0]), "=r"(r[1]), "=r"(r[2]), "=r"(r[3]) : "r"(addr));
}
__device__ __forceinline__ void ldsm_x4_t(uint32_t* r, uint32_t addr) {
    asm volatile("ldmatrix.sync.aligned.m8n8.x4.trans.shared.b16 {%0,%1,%2,%3}, [%4];"
                 : "=r"(r[0]), "=r"(r[1]), "=r"(r[2]), "=r"(r[3]) : "r"(addr));
}
__device__ __forceinline__ void mma16816(float* d, const uint32_t* a,
                                         uint32_t b0, uint32_t b1) {
    asm volatile(
        "mma.sync.aligned.m16n8k16.row.col.f32.bf16.bf16.f32 "
        "{%0,%1,%2,%3}, {%4,%5,%6,%7}, {%8,%9}, {%0,%1,%2,%3};"
        : "+f"(d[0]), "+f"(d[1]), "+f"(d[2]), "+f"(d[3])
        : "r"(a[0]), "r"(a[1]), "r"(a[2]), "r"(a[3]), "r"(b0), "r"(b1));
}
__device__ __forceinline__ void split2(float x0, float x1, uint32_t& hi, uint32_t& lo) {
    __nv_bfloat16 h0 = __float2bfloat16_rn(x0);
    __nv_bfloat16 h1 = __float2bfloat16_rn(x1);
    __nv_bfloat16 l0 = __float2bfloat16_rn(x0 - __bfloat162float(h0));
    __nv_bfloat16 l1 = __float2bfloat16_rn(x1 - __bfloat162float(h1));
    hi = (uint32_t)__bfloat16_as_ushort(h0) | ((uint32_t)__bfloat16_as_ushort(h1) << 16);
    lo = (uint32_t)__bfloat16_as_ushort(l0) | ((uint32_t)__bfloat16_as_ushort(l1) << 16);
}
__device__ __forceinline__ void cp16(uint32_t dst, const void* src) {
    asm volatile("cp.async.cg.shared.global [%0], [%1], 16;" :: "r"(dst), "l"(src));
}
#define CP_COMMIT() asm volatile("cp.async.commit_group;" ::: "memory")
#define CP_WAIT(n)  asm volatile("cp.async.wait_group %0;" :: "n"(n) : "memory")

// ===========================================================================
// split kernel: fp32 -> bf16 hi/lo (4 elements / thread)
// ===========================================================================
__global__ void __launch_bounds__(256)
split_kernel(const float* __restrict__ src, __nv_bfloat16* __restrict__ dh,
             __nv_bfloat16* __restrict__ dl)
{
    const int i = (blockIdx.x * 256 + threadIdx.x) * 4;
    float4 v = *reinterpret_cast<const float4*>(src + i);
    uint32_t h0, l0, h1, l1;
    split2(v.x, v.y, h0, l0);
    split2(v.z, v.w, h1, l1);
    *reinterpret_cast<uint2*>(dh + i) = make_uint2(h0, h1);
    *reinterpret_cast<uint2*>(dl + i) = make_uint2(l0, l1);
}

// ===========================================================================
// GEMM mainloop (bf16 pre-split inputs): acc = A @ W^T, 128x128x(D_) tile
// cp.async double-buffered, BK=32, 8 warps (2m x 4n).
// ===========================================================================
#define LDK_  40
#define GARR  10240                 // 128*40*2 bytes
#define GEMM_SMEM (8 * GARR)        // 80KB: 2 buffers x {Ah,Al,Wh,Wl}

__device__ __forceinline__ void gemm_body(
    const __nv_bfloat16* __restrict__ Ah, const __nv_bfloat16* __restrict__ Al,
    const __nv_bfloat16* __restrict__ Wh, const __nv_bfloat16* __restrict__ Wl,
    int m0, int n0, char* smem, float acc[4][4][4])
{
    const int tid    = threadIdx.x;
    const int lane   = tid & 31;
    const int wid    = tid >> 5;
    const int warp_m = wid & 1;
    const int warp_n = wid >> 1;
    const uint32_t sb = smem_u32(smem);

#pragma unroll
    for (int i = 0; i < 4; i++)
#pragma unroll
        for (int j = 0; j < 4; j++)
#pragma unroll
            for (int e = 0; e < 4; e++) acc[i][j][e] = 0.f;

    // cp.async mapping: row = tid>>1, two 16B chunks per thread per array
    const int grow = tid >> 1;
    const int c16  = (tid & 1) * 2;
    const __nv_bfloat16* s0 = Ah + (size_t)(m0 + grow) * D_;
    const __nv_bfloat16* s1 = Al + (size_t)(m0 + grow) * D_;
    const __nv_bfloat16* s2 = Wh + (size_t)(n0 + grow) * D_;
    const __nv_bfloat16* s3 = Wl + (size_t)(n0 + grow) * D_;

    auto issue = [&](int kc, int bsel) {
        const uint32_t dst = sb + bsel * 4 * GARR + grow * 80 + c16 * 16;
#pragma unroll
        for (int j = 0; j < 2; j++) {
            cp16(dst + j * 16,            s0 + kc + (c16 + j) * 8);
            cp16(dst + j * 16 + GARR,     s1 + kc + (c16 + j) * 8);
            cp16(dst + j * 16 + 2 * GARR, s2 + kc + (c16 + j) * 8);
            cp16(dst + j * 16 + 3 * GARR, s3 + kc + (c16 + j) * 8);
        }
    };

    // ldmatrix base offsets
    const int r_a = lane & 15, c_a = (lane >> 4) * 8;
    const int r_b = (lane & 7) | ((lane >> 4) << 3);
    const int c_b = ((lane >> 3) & 1) * 8;
    const uint32_t offA = ((warp_m * 64 + r_a) * LDK_ + c_a) * 2;
    const uint32_t offB = ((warp_n * 32 + r_b) * LDK_ + c_b) * 2;

    issue(0, 0);
    CP_COMMIT();

    const int NK = D_ / 32;   // 24
    for (int it = 0; it < NK; it++) {
        if (it + 1 < NK) {
            issue((it + 1) * 32, (it + 1) & 1);
            CP_COMMIT();
            CP_WAIT(1);
        } else {
            CP_WAIT(0);
        }
        __syncthreads();

        const uint32_t bAh = sb + ((it & 1) * 4 + 0) * GARR;
        const uint32_t bAl = bAh + GARR;
        const uint32_t bWh = bAh + 2 * GARR;
        const uint32_t bWl = bAh + 3 * GARR;

#pragma unroll
        for (int ks = 0; ks < 2; ks++) {
            const uint32_t ko = ks * 32;
            uint32_t ah[4][4], al[4][4];
#pragma unroll
            for (int mt = 0; mt < 4; mt++) {
                ldsm_x4(ah[mt], bAh + offA + ko + mt * 16 * LDK_ * 2);
                ldsm_x4(al[mt], bAl + offA + ko + mt * 16 * LDK_ * 2);
            }
            uint32_t bh[8], bl[8];
#pragma unroll
            for (int g = 0; g < 2; g++) {
                ldsm_x4(&bh[g * 4], bWh + offB + ko + g * 16 * LDK_ * 2);
                ldsm_x4(&bl[g * 4], bWl + offB + ko + g * 16 * LDK_ * 2);
            }
#pragma unroll
            for (int mt = 0; mt < 4; mt++)
#pragma unroll
                for (int nt = 0; nt < 4; nt++) {
                    mma16816(acc[mt][nt], ah[mt], bh[nt * 2], bh[nt * 2 + 1]);
                    mma16816(acc[mt][nt], ah[mt], bl[nt * 2], bl[nt * 2 + 1]);
                    mma16816(acc[mt][nt], al[mt], bh[nt * 2], bh[nt * 2 + 1]);
                }
        }
        __syncthreads();
    }
}

// fused QKV GEMM: grid.x = 18 (wsel = x/6), grid.y = 64
__global__ void __launch_bounds__(256, 2)
qkv_gemm(const float* __restrict__ bq, const float* __restrict__ bk,
         const float* __restrict__ bv)
{
    extern __shared__ char smem[];
    const int wsel = blockIdx.x / 6;
    const int n0   = (blockIdx.x % 6) * 128;
    const int m0   = blockIdx.y * 128;

    float acc[4][4][4];
    gemm_body(g_xh, g_xl, g_wh + (size_t)wsel * DD_, g_wl + (size_t)wsel * DD_,
              m0, n0, smem, acc);

    const float* bias = (wsel == 0) ? bq : (wsel == 1) ? bk : bv;
    float* out = (wsel == 0) ? g_q : (wsel == 1) ? g_k : g_v;

    const int lane = threadIdx.x & 31;
    const int wid  = threadIdx.x >> 5;
    const int warp_m = wid & 1, warp_n = wid >> 1;
#pragma unroll
    for (int mt = 0; mt < 4; mt++) {
#pragma unroll
        for (int nt = 0; nt < 4; nt++) {
            const int n = n0 + warp_n * 32 + nt * 8 + 2 * (lane & 3);
            const float2 bv2 = *reinterpret_cast<const float2*>(&bias[n]);
#pragma unroll
            for (int half = 0; half < 2; half++) {
                const int m = m0 + warp_m * 64 + mt * 16 + (lane >> 2) + half * 8;
                float2 o;
                o.x = acc[mt][nt][half * 2 + 0] + bv2.x;
                o.y = acc[mt][nt][half * 2 + 1] + bv2.y;
                const int bb = m >> 11, ss = m & (S_ - 1);
                const int hh = n >> 6,  dd = n & 63;
                *reinterpret_cast<float2*>(
                    out + (((size_t)(bb * H_ + hh)) * S_ + ss) * DH_ + dd) = o;
            }
        }
    }
}

// output GEMM: ctx(split) @ Wo^T + bo -> d_out
__global__ void __launch_bounds__(256, 2)
o_gemm(const float* __restrict__ bo, float* __restrict__ out)
{
    extern __shared__ char smem[];
    const int n0 = blockIdx.x * 128;
    const int m0 = blockIdx.y * 128;

    float acc[4][4][4];
    gemm_body(g_ch, g_cl, g_wh + 3 * (size_t)DD_, g_wl + 3 * (size_t)DD_,
              m0, n0, smem, acc);

    const int lane = threadIdx.x & 31;
    const int wid  = threadIdx.x >> 5;
    const int warp_m = wid & 1, warp_n = wid >> 1;
#pragma unroll
    for (int mt = 0; mt < 4; mt++) {
#pragma unroll
        for (int nt = 0; nt < 4; nt++) {
            const int n = n0 + warp_n * 32 + nt * 8 + 2 * (lane & 3);
            const float2 bv2 = *reinterpret_cast<const float2*>(&bo[n]);
#pragma unroll
            for (int half = 0; half < 2; half++) {
                const int m = m0 + warp_m * 64 + mt * 16 + (lane >> 2) + half * 8;
                float2 o;
                o.x = acc[mt][nt][half * 2 + 0] + bv2.x;
                o.y = acc[mt][nt][half * 2 + 1] + bv2.y;
                *reinterpret_cast<float2*>(out + (size_t)m * D_ + n) = o;
            }
        }
    }
}

// ===========================================================================
// Prep: normalize q,k (q scaled by per-head exp(min(ls,ln100))), split q,k,v
// ===========================================================================
__global__ void __launch_bounds__(256)
prep_kernel(const float* __restrict__ ls)
{
    const int gw   = (blockIdx.x * blockDim.x + threadIdx.x) >> 5;
    const int lane = threadIdx.x & 31;
    const int tensor = gw / NROWS_;
    const int row    = gw % NROWS_;

    const float* src;
    __nv_bfloat16 *dh, *dl;
    float sc = 1.f;
    bool donorm = true;
    if (tensor == 0) {
        src = g_q; dh = g_qh; dl = g_ql;
        const int hh = (row >> 11) % H_;
        sc = __expf(fminf(ls[hh], 4.6051701859880914f));
    } else if (tensor == 1) {
        src = g_k; dh = g_kh; dl = g_kl;
    } else {
        src = g_v; dh = g_vh; dl = g_vl; donorm = false;
    }
    const float* p = src + (size_t)row * DH_;
    float a = p[lane];
    float b = p[lane + 32];
    if (donorm) {
        float ss = a * a + b * b;
#pragma unroll
        for (int off = 16; off >= 1; off >>= 1)
            ss += __shfl_xor_sync(0xffffffffu, ss, off);
        const float inv = sc / fmaxf(sqrtf(ss), 1e-12f);
        a *= inv; b *= inv;
    }
    __nv_bfloat16 ah = __float2bfloat16_rn(a);
    __nv_bfloat16 bh = __float2bfloat16_rn(b);
    dh[(size_t)row * DH_ + lane]      = ah;
    dh[(size_t)row * DH_ + lane + 32] = bh;
    dl[(size_t)row * DH_ + lane]      = __float2bfloat16_rn(a - __bfloat162float(ah));
    dl[(size_t)row * DH_ + lane + 32] = __float2bfloat16_rn(b - __bfloat162float(bh));
}

// ===========================================================================
// HMMA flash attention (bf16x3), ctx written as bf16 hi/lo splits.
// ===========================================================================
#define ABUF   9216
#define ATTN_SMEM (8 * ABUF)

__global__ void __launch_bounds__(256, 2)
attn_mma()
{
    extern __shared__ char sm[];
    const uint32_t sbase = smem_u32(sm);
    const int tid  = threadIdx.x;
    const int lane = tid & 31;
    const int wid  = tid >> 5;
    const int bh   = blockIdx.y;
    const int h    = bh % H_;
    const int b    = bh / H_;
    const int q0   = blockIdx.x * 128;
    const size_t base = (size_t)bh * S_ * DH_;

    // stage Q hi/lo into smem, build A-fragments, release smem
    {
        const __nv_bfloat16* gq0 = g_qh + base + (size_t)q0 * DH_;
        const __nv_bfloat16* gq1 = g_ql + base + (size_t)q0 * DH_;
#pragma unroll
        for (int i = 0; i < 8; i++) {
            const int arr = i >> 2;
            const int idx = ((i & 3) << 8) + tid;
            const int row = idx >> 3, c = idx & 7;
            const uint4 v = *reinterpret_cast<const uint4*>(
                (arr ? gq1 : gq0) + row * DH_ + c * 8);
            *reinterpret_cast<uint4*>(sm + arr * 18432 + row * 144 + c * 16) = v;
        }
    }
    __syncthreads();
    uint32_t qfh[4][4], qfl[4][4];
    {
        const uint32_t qa = sbase + (wid * 16 + (lane & 15)) * 144 + (lane >> 4) * 16;
#pragma unroll
        for (int kt = 0; kt < 4; kt++) {
            ldsm_x4(qfh[kt], qa + kt * 32);
            ldsm_x4(qfl[kt], qa + 18432 + kt * 32);
        }
    }
    __syncthreads();

    float o[8][4];
#pragma unroll
    for (int nt = 0; nt < 8; nt++)
#pragma unroll
        for (int e = 0; e < 4; e++) o[nt][e] = 0.f;
    float m0 = -INFINITY, m1 = -INFINITY, l0 = 0.f, l1 = 0.f;

    const uint32_t lofs = (lane & 15) * 144 + (lane >> 4) * 16;

    const __nv_bfloat16* gkh = g_kh + base;
    const __nv_bfloat16* gkl = g_kl + base;
    const __nv_bfloat16* gvh = g_vh + base;
    const __nv_bfloat16* gvl = g_vl + base;

    auto issue = [&](int it, int bsel) {
        const int koff = it * 64 * DH_;
#pragma unroll
        for (int i = 0; i < 8; i++) {
            const int arr = i >> 1;
            const int idx = ((i & 1) << 8) + tid;
            const int row = idx >> 3, c = idx & 7;
            const __nv_bfloat16* gp =
                (arr == 0 ? gkh : arr == 1 ? gkl : arr == 2 ? gvh : gvl)
                + koff + row * DH_ + c * 8;
            cp16(sbase + (bsel * 4 + arr) * ABUF + row * 144 + c * 16, gp);
        }
    };

    issue(0, 0);
    CP_COMMIT();

    for (int it = 0; it < S_ / 64; it++) {
        if (it + 1 < S_ / 64) {
            issue(it + 1, (it + 1) & 1);
            CP_COMMIT();
            CP_WAIT(1);
        } else {
            CP_WAIT(0);
        }
        __syncthreads();

        const uint32_t Kh = sbase + (((it & 1) * 4 + 0) * ABUF);
        const uint32_t Kl = Kh + ABUF;
        const uint32_t Vh = Kh + 2 * ABUF;
        const uint32_t Vl = Kh + 3 * ABUF;

        float s[8][4];
#pragma unroll
        for (int nt = 0; nt < 8; nt++)
#pragma unroll
            for (int e = 0; e < 4; e++) s[nt][e] = 0.f;

#pragma unroll
        for (int kt = 0; kt < 4; kt++) {
#pragma unroll
            for (int g = 0; g < 4; g++) {
                uint32_t kf[4], lf[4];
                ldsm_x4(kf, Kh + lofs + g * 16 * 144 + kt * 32);
                ldsm_x4(lf, Kl + lofs + g * 16 * 144 + kt * 32);
                mma16816(s[2 * g],     qfh[kt], kf[0], kf[2]);
                mma16816(s[2 * g],     qfh[kt], lf[0], lf[2]);
                mma16816(s[2 * g],     qfl[kt], kf[0], kf[2]);
                mma16816(s[2 * g + 1], qfh[kt], kf[1], kf[3]);
                mma16816(s[2 * g + 1], qfh[kt], lf[1], lf[3]);
                mma16816(s[2 * g + 1], qfl[kt], kf[1], kf[3]);
            }
        }

        float a0 = -INFINITY, a1 = -INFINITY;
#pragma unroll
        for (int nt = 0; nt < 8; nt++) {
            a0 = fmaxf(a0, fmaxf(s[nt][0], s[nt][1]));
            a1 = fmaxf(a1, fmaxf(s[nt][2], s[nt][3]));
        }
        a0 = fmaxf(a0, __shfl_xor_sync(0xffffffffu, a0, 1));
        a0 = fmaxf(a0, __shfl_xor_sync(0xffffffffu, a0, 2));
        a1 = fmaxf(a1, __shfl_xor_sync(0xffffffffu, a1, 1));
        a1 = fmaxf(a1, __shfl_xor_sync(0xffffffffu, a1, 2));
        const float mn0 = fmaxf(m0, a0);
        const float mn1 = fmaxf(m1, a1);
        const float al0 = __expf(m0 - mn0);
        const float al1 = __expf(m1 - mn1);
        m0 = mn0; m1 = mn1;
        l0 *= al0; l1 *= al1;
#pragma unroll
        for (int nt = 0; nt < 8; nt++) {
            o[nt][0] *= al0; o[nt][1] *= al0;
            o[nt][2] *= al1; o[nt][3] *= al1;
        }
        float sum0 = 0.f, sum1 = 0.f;
#pragma unroll
        for (int nt = 0; nt < 8; nt++) {
            s[nt][0] = __expf(s[nt][0] - mn0);
            s[nt][1] = __expf(s[nt][1] - mn0);
            s[nt][2] = __expf(s[nt][2] - mn1);
            s[nt][3] = __expf(s[nt][3] - mn1);
            sum0 += s[nt][0] + s[nt][1];
            sum1 += s[nt][2] + s[nt][3];
        }
        sum0 += __shfl_xor_sync(0xffffffffu, sum0, 1);
        sum0 += __shfl_xor_sync(0xffffffffu, sum0, 2);
        sum1 += __shfl_xor_sync(0xffffffffu, sum1, 1);
        sum1 += __shfl_xor_sync(0xffffffffu, sum1, 2);
        l0 += sum0; l1 += sum1;

#pragma unroll
        for (int kt = 0; kt < 4; kt++) {
            uint32_t ah[4], al[4];
            split2(s[2 * kt][0],     s[2 * kt][1],     ah[0], al[0]);
            split2(s[2 * kt][2],     s[2 * kt][3],     ah[1], al[1]);
            split2(s[2 * kt + 1][0], s[2 * kt + 1][1], ah[2], al[2]);
            split2(s[2 * kt + 1][2], s[2 * kt + 1][3], ah[3], al[3]);
#pragma unroll
            for (int g = 0; g < 4; g++) {
                uint32_t vf[4], wf[4];
                ldsm_x4_t(vf, Vh + lofs + kt * 16 * 144 + g * 32);
                ldsm_x4_t(wf, Vl + lofs + kt * 16 * 144 + g * 32);
                mma16816(o[2 * g],     ah, vf[0], vf[1]);
                mma16816(o[2 * g],     ah, wf[0], wf[1]);
                mma16816(o[2 * g],     al, vf[0], vf[1]);
                mma16816(o[2 * g + 1], ah, vf[2], vf[3]);
                mma16816(o[2 * g + 1], ah, wf[2], wf[3]);
                mma16816(o[2 * g + 1], al, vf[2], vf[3]);
            }
        }
        __syncthreads();
    }

    // epilogue: write ctx as bf16 hi/lo splits
    const float inv0 = 1.f / l0;
    const float inv1 = 1.f / l1;
    const int row0 = q0 + wid * 16 + (lane >> 2);
    const int col0 = h * DH_ + 2 * (lane & 3);
    const size_t p0 = ((size_t)b * S_ + row0) * D_ + col0;
    const size_t p1 = p0 + 8 * D_;
#pragma unroll
    for (int nt = 0; nt < 8; nt++) {
        uint32_t hi, lo;
        split2(o[nt][0] * inv0, o[nt][1] * inv0, hi, lo);
        *reinterpret_cast<uint32_t*>(g_ch + p0 + nt * 8) = hi;
        *reinterpret_cast<uint32_t*>(g_cl + p0 + nt * 8) = lo;
        split2(o[nt][2] * inv1, o[nt][3] * inv1, hi, lo);
        *reinterpret_cast<uint32_t*>(g_ch + p1 + nt * 8) = hi;
        *reinterpret_cast<uint32_t*>(g_cl + p1 + nt * 8) = lo;
    }
}

// ---------------------------------------------------------------------------
// Launch
// ---------------------------------------------------------------------------
extern "C" void kernel_launch(void* const* d_in, const int* in_sizes, int n_in,
                              void* d_out, int out_size)
{
    const float* x  = (const float*)d_in[0];
    const float* Wq = (const float*)d_in[1];
    const float* bq = (const float*)d_in[2];
    const float* Wk = (const float*)d_in[3];
    const float* bk = (const float*)d_in[4];
    const float* Wv = (const float*)d_in[5];
    const float* bv = (const float*)d_in[6];
    const float* Wo = (const float*)d_in[7];
    const float* bo = (const float*)d_in[8];
    const float* ls = (const float*)d_in[9];
    float* out = (float*)d_out;

    __nv_bfloat16 *xh, *xl, *wh, *wl;
    cudaGetSymbolAddress((void**)&xh, g_xh);
    cudaGetSymbolAddress((void**)&xl, g_xl);
    cudaGetSymbolAddress((void**)&wh, g_wh);
    cudaGetSymbolAddress((void**)&wl, g_wl);

    // pre-split x and the 4 weight matrices
    split_kernel<<<(M_ * D_) / 1024, 256>>>(x,  xh, xl);
    split_kernel<<<DD_ / 1024, 256>>>(Wq, wh + 0 * DD_, wl + 0 * DD_);
    split_kernel<<<DD_ / 1024, 256>>>(Wk, wh + 1 * (size_t)DD_, wl + 1 * (size_t)DD_);
    split_kernel<<<DD_ / 1024, 256>>>(Wv, wh + 2 * (size_t)DD_, wl + 2 * (size_t)DD_);
    split_kernel<<<DD_ / 1024, 256>>>(Wo, wh + 3 * (size_t)DD_, wl + 3 * (size_t)DD_);

    cudaFuncSetAttribute(qkv_gemm, cudaFuncAttributeMaxDynamicSharedMemorySize, GEMM_SMEM);
    cudaFuncSetAttribute(o_gemm,   cudaFuncAttributeMaxDynamicSharedMemorySize, GEMM_SMEM);
    cudaFuncSetAttribute(attn_mma, cudaFuncAttributeMaxDynamicSharedMemorySize, ATTN_SMEM);

    qkv_gemm<<<dim3(18, M_ / 128), 256, GEMM_SMEM>>>(bq, bk, bv);

    prep_kernel<<<(3 * NROWS_) / 8, 256>>>(ls);

    attn_mma<<<dim3(S_ / 128, B_ * H_), 256, ATTN_SMEM>>>();

    o_gemm<<<dim3(D_ / 128, M_ / 128), 256, GEMM_SMEM>>>(bo, out);
}

// round 6
// speedup vs baseline: 3.1131x; 1.0650x over previous
#include <cuda_runtime.h>
#include <cuda_bf16.h>
#include <math.h>
#include <cstdint>

#define B_  4
#define S_  2048
#define D_  768
#define H_  12
#define DH_ 64
#define M_  (B_*S_)          // 8192
#define NROWS_ (B_*H_*S_)    // 98304
#define QKVN_ (NROWS_*DH_)   // 6291456
#define DD_  (D_*D_)         // 589824
#define LOG2E_ 1.4426950408889634f

// Scratch (allocation-free: static __device__ globals)
__device__ __nv_bfloat16 g_xh[M_*D_],  g_xl[M_*D_];
__device__ __nv_bfloat16 g_wh[4*DD_],  g_wl[4*DD_];
__device__ __nv_bfloat16 g_qh[QKVN_],  g_ql[QKVN_];
__device__ __nv_bfloat16 g_kh[QKVN_],  g_kl[QKVN_];
__device__ __nv_bfloat16 g_vh[QKVN_],  g_vl[QKVN_];
__device__ __nv_bfloat16 g_ch[M_*D_],  g_cl[M_*D_];

// ===========================================================================
// Helpers
// ===========================================================================
__device__ __forceinline__ uint32_t smem_u32(const void* p) {
    uint32_t r;
    asm("{ .reg .u64 t; cvta.to.shared.u64 t, %1; cvt.u32.u64 %0, t; }"
        : "=r"(r) : "l"(p));
    return r;
}
__device__ __forceinline__ void ldsm_x4(uint32_t* r, uint32_t addr) {
    asm volatile("ldmatrix.sync.aligned.m8n8.x4.shared.b16 {%0,%1,%2,%3}, [%4];"
                 : "=r"(r[0]), "=r"(r[1]), "=r"(r[2]), "=r"(r[3]) : "r"(addr));
}
__device__ __forceinline__ void ldsm_x4_t(uint32_t* r, uint32_t addr) {
    asm volatile("ldmatrix.sync.aligned.m8n8.x4.trans.shared.b16 {%0,%1,%2,%3}, [%4];"
                 : "=r"(r[0]), "=r"(r[1]), "=r"(r[2]), "=r"(r[3]) : "r"(addr));
}
__device__ __forceinline__ void mma16816(float* d, const uint32_t* a,
                                         uint32_t b0, uint32_t b1) {
    asm volatile(
        "mma.sync.aligned.m16n8k16.row.col.f32.bf16.bf16.f32 "
        "{%0,%1,%2,%3}, {%4,%5,%6,%7}, {%8,%9}, {%0,%1,%2,%3};"
        : "+f"(d[0]), "+f"(d[1]), "+f"(d[2]), "+f"(d[3])
        : "r"(a[0]), "r"(a[1]), "r"(a[2]), "r"(a[3]), "r"(b0), "r"(b1));
}
// round-to-nearest hi/lo split (used off the hot path)
__device__ __forceinline__ void split2(float x0, float x1, uint32_t& hi, uint32_t& lo) {
    __nv_bfloat16 h0 = __float2bfloat16_rn(x0);
    __nv_bfloat16 h1 = __float2bfloat16_rn(x1);
    __nv_bfloat16 l0 = __float2bfloat16_rn(x0 - __bfloat162float(h0));
    __nv_bfloat16 l1 = __float2bfloat16_rn(x1 - __bfloat162float(h1));
    hi = (uint32_t)__bfloat16_as_ushort(h0) | ((uint32_t)__bfloat16_as_ushort(h1) << 16);
    lo = (uint32_t)__bfloat16_as_ushort(l0) | ((uint32_t)__bfloat16_as_ushort(l1) << 16);
}
// cheap truncation split for softmax P (hot path): 6 instrs / pair
__device__ __forceinline__ void psplit(float x0, float x1, uint32_t& hi, uint32_t& lo) {
    const uint32_t u0 = __float_as_uint(x0), u1 = __float_as_uint(x1);
    hi = __byte_perm(u0, u1, 0x7632);
    const float l0 = x0 - __uint_as_float(u0 & 0xFFFF0000u);
    const float l1 = x1 - __uint_as_float(u1 & 0xFFFF0000u);
    asm("cvt.rn.bf16x2.f32 %0, %1, %2;" : "=r"(lo) : "f"(l1), "f"(l0));
}
__device__ __forceinline__ float ex2(float x) {
    float y;
    asm("ex2.approx.f32 %0, %1;" : "=f"(y) : "f"(x));
    return y;
}
__device__ __forceinline__ void cp16(uint32_t dst, const void* src) {
    asm volatile("cp.async.cg.shared.global [%0], [%1], 16;" :: "r"(dst), "l"(src));
}
#define CP_COMMIT() asm volatile("cp.async.commit_group;" ::: "memory")
#define CP_WAIT(n)  asm volatile("cp.async.wait_group %0;" :: "n"(n) : "memory")

// ===========================================================================
// split kernels: fp32 -> bf16 hi/lo
// ===========================================================================
__global__ void __launch_bounds__(256)
xsplit_kernel(const float* __restrict__ src)
{
    const int i = (blockIdx.x * 256 + threadIdx.x) * 4;
    float4 v = *reinterpret_cast<const float4*>(src + i);
    uint32_t h0, l0, h1, l1;
    split2(v.x, v.y, h0, l0);
    split2(v.z, v.w, h1, l1);
    *reinterpret_cast<uint2*>(g_xh + i) = make_uint2(h0, h1);
    *reinterpret_cast<uint2*>(g_xl + i) = make_uint2(l0, l1);
}
__global__ void __launch_bounds__(256)
wsplit_kernel(const float* __restrict__ Wq, const float* __restrict__ Wk,
              const float* __restrict__ Wv, const float* __restrict__ Wo)
{
    const int per = DD_ / 1024;                   // 576
    const int wsel = blockIdx.x / per;
    const int bx   = blockIdx.x % per;
    const float* src = (wsel == 0) ? Wq : (wsel == 1) ? Wk : (wsel == 2) ? Wv : Wo;
    const int i = (bx * 256 + threadIdx.x) * 4;
    float4 v = *reinterpret_cast<const float4*>(src + i);
    uint32_t h0, l0, h1, l1;
    split2(v.x, v.y, h0, l0);
    split2(v.z, v.w, h1, l1);
    const size_t o = (size_t)wsel * DD_ + i;
    *reinterpret_cast<uint2*>(g_wh + o) = make_uint2(h0, h1);
    *reinterpret_cast<uint2*>(g_wl + o) = make_uint2(l0, l1);
}

// ===========================================================================
// GEMM mainloop (bf16 pre-split inputs): acc = A @ W^T, 128x128 tile
// ===========================================================================
#define LDK_  40
#define GARR  10240
#define GEMM_SMEM (8 * GARR)        // 80KB

__device__ __forceinline__ void gemm_body(
    const __nv_bfloat16* __restrict__ Ah, const __nv_bfloat16* __restrict__ Al,
    const __nv_bfloat16* __restrict__ Wh, const __nv_bfloat16* __restrict__ Wl,
    int m0, int n0, char* smem, float acc[4][4][4])
{
    const int tid    = threadIdx.x;
    const int lane   = tid & 31;
    const int wid    = tid >> 5;
    const int warp_m = wid & 1;
    const int warp_n = wid >> 1;
    const uint32_t sb = smem_u32(smem);

#pragma unroll
    for (int i = 0; i < 4; i++)
#pragma unroll
        for (int j = 0; j < 4; j++)
#pragma unroll
            for (int e = 0; e < 4; e++) acc[i][j][e] = 0.f;

    const int grow = tid >> 1;
    const int c16  = (tid & 1) * 2;
    const __nv_bfloat16* s0 = Ah + (size_t)(m0 + grow) * D_;
    const __nv_bfloat16* s1 = Al + (size_t)(m0 + grow) * D_;
    const __nv_bfloat16* s2 = Wh + (size_t)(n0 + grow) * D_;
    const __nv_bfloat16* s3 = Wl + (size_t)(n0 + grow) * D_;

    auto issue = [&](int kc, int bsel) {
        const uint32_t dst = sb + bsel * 4 * GARR + grow * 80 + c16 * 16;
#pragma unroll
        for (int j = 0; j < 2; j++) {
            cp16(dst + j * 16,            s0 + kc + (c16 + j) * 8);
            cp16(dst + j * 16 + GARR,     s1 + kc + (c16 + j) * 8);
            cp16(dst + j * 16 + 2 * GARR, s2 + kc + (c16 + j) * 8);
            cp16(dst + j * 16 + 3 * GARR, s3 + kc + (c16 + j) * 8);
        }
    };

    const int r_a = lane & 15, c_a = (lane >> 4) * 8;
    const int r_b = (lane & 7) | ((lane >> 4) << 3);
    const int c_b = ((lane >> 3) & 1) * 8;
    const uint32_t offA = ((warp_m * 64 + r_a) * LDK_ + c_a) * 2;
    const uint32_t offB = ((warp_n * 32 + r_b) * LDK_ + c_b) * 2;

    issue(0, 0);
    CP_COMMIT();

    const int NK = D_ / 32;   // 24
    for (int it = 0; it < NK; it++) {
        if (it + 1 < NK) {
            issue((it + 1) * 32, (it + 1) & 1);
            CP_COMMIT();
            CP_WAIT(1);
        } else {
            CP_WAIT(0);
        }
        __syncthreads();

        const uint32_t bAh = sb + ((it & 1) * 4 + 0) * GARR;
        const uint32_t bAl = bAh + GARR;
        const uint32_t bWh = bAh + 2 * GARR;
        const uint32_t bWl = bAh + 3 * GARR;

#pragma unroll
        for (int ks = 0; ks < 2; ks++) {
            const uint32_t ko = ks * 32;
            uint32_t ah[4][4], al[4][4];
#pragma unroll
            for (int mt = 0; mt < 4; mt++) {
                ldsm_x4(ah[mt], bAh + offA + ko + mt * 16 * LDK_ * 2);
                ldsm_x4(al[mt], bAl + offA + ko + mt * 16 * LDK_ * 2);
            }
            uint32_t bh[8], bl[8];
#pragma unroll
            for (int g = 0; g < 2; g++) {
                ldsm_x4(&bh[g * 4], bWh + offB + ko + g * 16 * LDK_ * 2);
                ldsm_x4(&bl[g * 4], bWl + offB + ko + g * 16 * LDK_ * 2);
            }
#pragma unroll
            for (int mt = 0; mt < 4; mt++)
#pragma unroll
                for (int nt = 0; nt < 4; nt++) {
                    mma16816(acc[mt][nt], ah[mt], bh[nt * 2], bh[nt * 2 + 1]);
                    mma16816(acc[mt][nt], ah[mt], bl[nt * 2], bl[nt * 2 + 1]);
                    mma16816(acc[mt][nt], al[mt], bh[nt * 2], bh[nt * 2 + 1]);
                }
        }
        __syncthreads();
    }
}

// ===========================================================================
// fused QKV GEMM: proj + bias + (L2 norm + scale for q,k) + bf16 split store.
// grid.x = 18 (wsel = x/6), grid.y = 64. q gets scale*log2e prefolded.
// ===========================================================================
__global__ void __launch_bounds__(256, 2)
qkv_gemm(const float* __restrict__ bq, const float* __restrict__ bk,
         const float* __restrict__ bv, const float* __restrict__ ls)
{
    extern __shared__ char smem[];
    const int wsel = blockIdx.x / 6;
    const int n0   = (blockIdx.x % 6) * 128;
    const int m0   = blockIdx.y * 128;

    float acc[4][4][4];
    gemm_body(g_xh, g_xl, g_wh + (size_t)wsel * DD_, g_wl + (size_t)wsel * DD_,
              m0, n0, smem, acc);

    const int tid  = threadIdx.x;
    const int lane = tid & 31;
    const int wid  = tid >> 5;
    const int warp_m = wid & 1, warp_n = wid >> 1;

    const float* bias = (wsel == 0) ? bq : (wsel == 1) ? bk : bv;
    __nv_bfloat16* dh = (wsel == 0) ? g_qh : (wsel == 1) ? g_kh : g_vh;
    __nv_bfloat16* dl = (wsel == 0) ? g_ql : (wsel == 1) ? g_kl : g_vl;

    // bias add
    float2 bv2[4];
#pragma unroll
    for (int nt = 0; nt < 4; nt++)
        bv2[nt] = *reinterpret_cast<const float2*>(
            &bias[n0 + warp_n * 32 + nt * 8 + 2 * (lane & 3)]);
#pragma unroll
    for (int mt = 0; mt < 4; mt++)
#pragma unroll
        for (int nt = 0; nt < 4; nt++) {
            acc[mt][nt][0] += bv2[nt].x; acc[mt][nt][1] += bv2[nt].y;
            acc[mt][nt][2] += bv2[nt].x; acc[mt][nt][3] += bv2[nt].y;
        }

    __syncthreads();   // smem reuse safety (mainloop done)
    float* sq = reinterpret_cast<float*>(smem);   // [128][4]

    if (wsel < 2) {
#pragma unroll
        for (int mt = 0; mt < 4; mt++)
#pragma unroll
            for (int half = 0; half < 2; half++) {
                const int r = warp_m * 64 + mt * 16 + (lane >> 2) + half * 8;
                float p = 0.f;
#pragma unroll
                for (int nt = 0; nt < 4; nt++) {
                    const float a = acc[mt][nt][half * 2], bvv = acc[mt][nt][half * 2 + 1];
                    p += a * a + bvv * bvv;
                }
                p += __shfl_xor_sync(0xffffffffu, p, 1);
                p += __shfl_xor_sync(0xffffffffu, p, 2);
                if ((lane & 3) == 0) sq[r * 4 + warp_n] = p;
            }
        __syncthreads();
    }

    // per-head scale (q only): exp(min(ls,ln100)) * log2e
    float scl = 1.f;
    if (wsel == 0) {
        const int hh = 2 * (blockIdx.x % 6) + (warp_n >> 1);
        scl = __expf(fminf(ls[hh], 4.6051701859880914f)) * LOG2E_;
    }

#pragma unroll
    for (int mt = 0; mt < 4; mt++) {
#pragma unroll
        for (int half = 0; half < 2; half++) {
            const int r = warp_m * 64 + mt * 16 + (lane >> 2) + half * 8;
            float inv = 1.f;
            if (wsel < 2) {
                const float s2 = sq[r * 4 + (warp_n & 2)] + sq[r * 4 + (warp_n & 2) + 1];
                inv = scl / fmaxf(sqrtf(s2), 1e-12f);
            }
            const int m  = m0 + r;
            const int bb = m >> 11, ss = m & (S_ - 1);
#pragma unroll
            for (int nt = 0; nt < 4; nt++) {
                const int n  = n0 + warp_n * 32 + nt * 8 + 2 * (lane & 3);
                const int hh = n >> 6, dd = n & 63;
                const size_t idx = (((size_t)(bb * H_ + hh)) * S_ + ss) * DH_ + dd;
                uint32_t hi, lo;
                split2(acc[mt][nt][half * 2] * inv, acc[mt][nt][half * 2 + 1] * inv, hi, lo);
                *reinterpret_cast<uint32_t*>(&dh[idx]) = hi;
                *reinterpret_cast<uint32_t*>(&dl[idx]) = lo;
            }
        }
    }
}

// output GEMM: ctx(split) @ Wo^T + bo -> d_out
__global__ void __launch_bounds__(256, 2)
o_gemm(const float* __restrict__ bo, float* __restrict__ out)
{
    extern __shared__ char smem[];
    const int n0 = blockIdx.x * 128;
    const int m0 = blockIdx.y * 128;

    float acc[4][4][4];
    gemm_body(g_ch, g_cl, g_wh + 3 * (size_t)DD_, g_wl + 3 * (size_t)DD_,
              m0, n0, smem, acc);

    const int lane = threadIdx.x & 31;
    const int wid  = threadIdx.x >> 5;
    const int warp_m = wid & 1, warp_n = wid >> 1;
#pragma unroll
    for (int mt = 0; mt < 4; mt++) {
#pragma unroll
        for (int nt = 0; nt < 4; nt++) {
            const int n = n0 + warp_n * 32 + nt * 8 + 2 * (lane & 3);
            const float2 bv2 = *reinterpret_cast<const float2*>(&bo[n]);
#pragma unroll
            for (int half = 0; half < 2; half++) {
                const int m = m0 + warp_m * 64 + mt * 16 + (lane >> 2) + half * 8;
                float2 o;
                o.x = acc[mt][nt][half * 2 + 0] + bv2.x;
                o.y = acc[mt][nt][half * 2 + 1] + bv2.y;
                *reinterpret_cast<float2*>(out + (size_t)m * D_ + n) = o;
            }
        }
    }
}

// ===========================================================================
// HMMA flash attention (bf16x3), exp2-domain softmax, 3-deep cp.async ring.
// ===========================================================================
#define ABUF   9216
#define ATTN_SMEM (12 * ABUF)      // 3 buffers x {Kh,Kl,Vh,Vl}

__global__ void __launch_bounds__(256, 2)
attn_mma()
{
    extern __shared__ char sm[];
    const uint32_t sbase = smem_u32(sm);
    const int tid  = threadIdx.x;
    const int lane = tid & 31;
    const int wid  = tid >> 5;
    const int bh   = blockIdx.y;
    const int h    = bh % H_;
    const int b    = bh / H_;
    const int q0   = blockIdx.x * 128;
    const size_t base = (size_t)bh * S_ * DH_;

    // stage Q hi/lo into smem (first 36KB), build A-fragments, release
    {
        const __nv_bfloat16* gq0 = g_qh + base + (size_t)q0 * DH_;
        const __nv_bfloat16* gq1 = g_ql + base + (size_t)q0 * DH_;
#pragma unroll
        for (int i = 0; i < 8; i++) {
            const int arr = i >> 2;
            const int idx = ((i & 3) << 8) + tid;
            const int row = idx >> 3, c = idx & 7;
            const uint4 v = *reinterpret_cast<const uint4*>(
                (arr ? gq1 : gq0) + row * DH_ + c * 8);
            *reinterpret_cast<uint4*>(sm + arr * 18432 + row * 144 + c * 16) = v;
        }
    }
    __syncthreads();
    uint32_t qfh[4][4], qfl[4][4];
    {
        const uint32_t qa = sbase + (wid * 16 + (lane & 15)) * 144 + (lane >> 4) * 16;
#pragma unroll
        for (int kt = 0; kt < 4; kt++) {
            ldsm_x4(qfh[kt], qa + kt * 32);
            ldsm_x4(qfl[kt], qa + 18432 + kt * 32);
        }
    }
    __syncthreads();

    float o[8][4];
#pragma unroll
    for (int nt = 0; nt < 8; nt++)
#pragma unroll
        for (int e = 0; e < 4; e++) o[nt][e] = 0.f;
    float m0 = -INFINITY, m1 = -INFINITY, l0 = 0.f, l1 = 0.f;

    const uint32_t lofs = (lane & 15) * 144 + (lane >> 4) * 16;

    const __nv_bfloat16* gkh = g_kh + base;
    const __nv_bfloat16* gkl = g_kl + base;
    const __nv_bfloat16* gvh = g_vh + base;
    const __nv_bfloat16* gvl = g_vl + base;

    auto issue = [&](int it, int bsel) {
        const int koff = it * 64 * DH_;
#pragma unroll
        for (int i = 0; i < 8; i++) {
            const int arr = i >> 1;
            const int idx = ((i & 1) << 8) + tid;
            const int row = idx >> 3, c = idx & 7;
            const __nv_bfloat16* gp =
                (arr == 0 ? gkh : arr == 1 ? gkl : arr == 2 ? gvh : gvl)
                + koff + row * DH_ + c * 8;
            cp16(sbase + (bsel * 4 + arr) * ABUF + row * 144 + c * 16, gp);
        }
    };

    issue(0, 0); CP_COMMIT();
    issue(1, 1); CP_COMMIT();

    const int NIT = S_ / 64;   // 32
    for (int it = 0; it < NIT; it++) {
        if (it + 1 < NIT) { CP_WAIT(1); } else { CP_WAIT(0); }
        __syncthreads();                       // all reads of buf (it-1)%3 done
        if (it + 2 < NIT) { issue(it + 2, (it + 2) % 3); CP_COMMIT(); }

        const uint32_t Kh = sbase + ((it % 3) * 4) * ABUF;
        const uint32_t Kl = Kh + ABUF;
        const uint32_t Vh = Kh + 2 * ABUF;
        const uint32_t Vl = Kh + 3 * ABUF;

        // ---- S' = Q' @ K^T  (scale*log2e prefolded into q)
        float s[8][4];
#pragma unroll
        for (int nt = 0; nt < 8; nt++)
#pragma unroll
            for (int e = 0; e < 4; e++) s[nt][e] = 0.f;

#pragma unroll
        for (int kt = 0; kt < 4; kt++) {
#pragma unroll
            for (int g = 0; g < 4; g++) {
                uint32_t kf[4], lf[4];
                ldsm_x4(kf, Kh + lofs + g * 16 * 144 + kt * 32);
                ldsm_x4(lf, Kl + lofs + g * 16 * 144 + kt * 32);
                mma16816(s[2 * g],     qfh[kt], kf[0], kf[2]);
                mma16816(s[2 * g],     qfh[kt], lf[0], lf[2]);
                mma16816(s[2 * g],     qfl[kt], kf[0], kf[2]);
                mma16816(s[2 * g + 1], qfh[kt], kf[1], kf[3]);
                mma16816(s[2 * g + 1], qfh[kt], lf[1], lf[3]);
                mma16816(s[2 * g + 1], qfl[kt], kf[1], kf[3]);
            }
        }

        // ---- online softmax in exp2 domain
        float a0 = -INFINITY, a1 = -INFINITY;
#pragma unroll
        for (int nt = 0; nt < 8; nt++) {
            a0 = fmaxf(a0, fmaxf(s[nt][0], s[nt][1]));
            a1 = fmaxf(a1, fmaxf(s[nt][2], s[nt][3]));
        }
        a0 = fmaxf(a0, __shfl_xor_sync(0xffffffffu, a0, 1));
        a0 = fmaxf(a0, __shfl_xor_sync(0xffffffffu, a0, 2));
        a1 = fmaxf(a1, __shfl_xor_sync(0xffffffffu, a1, 1));
        a1 = fmaxf(a1, __shfl_xor_sync(0xffffffffu, a1, 2));
        const float mn0 = fmaxf(m0, a0);
        const float mn1 = fmaxf(m1, a1);
        const float al0 = ex2(m0 - mn0);
        const float al1 = ex2(m1 - mn1);
        m0 = mn0; m1 = mn1;
        l0 *= al0; l1 *= al1;
#pragma unroll
        for (int nt = 0; nt < 8; nt++) {
            o[nt][0] *= al0; o[nt][1] *= al0;
            o[nt][2] *= al1; o[nt][3] *= al1;
        }
        float sum0 = 0.f, sum1 = 0.f;
#pragma unroll
        for (int nt = 0; nt < 8; nt++) {
            s[nt][0] = ex2(s[nt][0] - mn0);
            s[nt][1] = ex2(s[nt][1] - mn0);
            s[nt][2] = ex2(s[nt][2] - mn1);
            s[nt][3] = ex2(s[nt][3] - mn1);
            sum0 += s[nt][0] + s[nt][1];
            sum1 += s[nt][2] + s[nt][3];
        }
        sum0 += __shfl_xor_sync(0xffffffffu, sum0, 1);
        sum0 += __shfl_xor_sync(0xffffffffu, sum0, 2);
        sum1 += __shfl_xor_sync(0xffffffffu, sum1, 1);
        sum1 += __shfl_xor_sync(0xffffffffu, sum1, 2);
        l0 += sum0; l1 += sum1;

        // ---- O += P @ V  (cheap truncation split for P)
#pragma unroll
        for (int kt = 0; kt < 4; kt++) {
            uint32_t ah[4], al[4];
            psplit(s[2 * kt][0],     s[2 * kt][1],     ah[0], al[0]);
            psplit(s[2 * kt][2],     s[2 * kt][3],     ah[1], al[1]);
            psplit(s[2 * kt + 1][0], s[2 * kt + 1][1], ah[2], al[2]);
            psplit(s[2 * kt + 1][2], s[2 * kt + 1][3], ah[3], al[3]);
#pragma unroll
            for (int g = 0; g < 4; g++) {
                uint32_t vf[4], wf[4];
                ldsm_x4_t(vf, Vh + lofs + kt * 16 * 144 + g * 32);
                ldsm_x4_t(wf, Vl + lofs + kt * 16 * 144 + g * 32);
                mma16816(o[2 * g],     ah, vf[0], vf[1]);
                mma16816(o[2 * g],     ah, wf[0], wf[1]);
                mma16816(o[2 * g],     al, vf[0], vf[1]);
                mma16816(o[2 * g + 1], ah, vf[2], vf[3]);
                mma16816(o[2 * g + 1], ah, wf[2], wf[3]);
                mma16816(o[2 * g + 1], al, vf[2], vf[3]);
            }
        }
    }

    // epilogue: write ctx as bf16 hi/lo splits
    const float inv0 = 1.f / l0;
    const float inv1 = 1.f / l1;
    const int row0 = q0 + wid * 16 + (lane >> 2);
    const int col0 = h * DH_ + 2 * (lane & 3);
    const size_t p0 = ((size_t)b * S_ + row0) * D_ + col0;
    const size_t p1 = p0 + 8 * D_;
#pragma unroll
    for (int nt = 0; nt < 8; nt++) {
        uint32_t hi, lo;
        split2(o[nt][0] * inv0, o[nt][1] * inv0, hi, lo);
        *reinterpret_cast<uint32_t*>(g_ch + p0 + nt * 8) = hi;
        *reinterpret_cast<uint32_t*>(g_cl + p0 + nt * 8) = lo;
        split2(o[nt][2] * inv1, o[nt][3] * inv1, hi, lo);
        *reinterpret_cast<uint32_t*>(g_ch + p1 + nt * 8) = hi;
        *reinterpret_cast<uint32_t*>(g_cl + p1 + nt * 8) = lo;
    }
}

// ---------------------------------------------------------------------------
// Launch
// ---------------------------------------------------------------------------
extern "C" void kernel_launch(void* const* d_in, const int* in_sizes, int n_in,
                              void* d_out, int out_size)
{
    const float* x  = (const float*)d_in[0];
    const float* Wq = (const float*)d_in[1];
    const float* bq = (const float*)d_in[2];
    const float* Wk = (const float*)d_in[3];
    const float* bk = (const float*)d_in[4];
    const float* Wv = (const float*)d_in[5];
    const float* bv = (const float*)d_in[6];
    const float* Wo = (const float*)d_in[7];
    const float* bo = (const float*)d_in[8];
    const float* ls = (const float*)d_in[9];
    float* out = (float*)d_out;

    xsplit_kernel<<<(M_ * D_) / 1024, 256>>>(x);
    wsplit_kernel<<<4 * (DD_ / 1024), 256>>>(Wq, Wk, Wv, Wo);

    cudaFuncSetAttribute(qkv_gemm, cudaFuncAttributeMaxDynamicSharedMemorySize, GEMM_SMEM);
    cudaFuncSetAttribute(o_gemm,   cudaFuncAttributeMaxDynamicSharedMemorySize, GEMM_SMEM);
    cudaFuncSetAttribute(attn_mma, cudaFuncAttributeMaxDynamicSharedMemorySize, ATTN_SMEM);

    qkv_gemm<<<dim3(18, M_ / 128), 256, GEMM_SMEM>>>(bq, bk, bv, ls);

    attn_mma<<<dim3(S_ / 128, B_ * H_), 256, ATTN_SMEM>>>();

    o_gemm<<<dim3(D_ / 128, M_ / 128), 256, GEMM_SMEM>>>(bo, out);
}

// round 7
// speedup vs baseline: 3.1998x; 1.0279x over previous
#include <cuda_runtime.h>
#include <cuda_bf16.h>
#include <math.h>
#include <cstdint>

#define B_  4
#define S_  2048
#define D_  768
#define H_  12
#define DH_ 64
#define M_  (B_*S_)          // 8192
#define NROWS_ (B_*H_*S_)    // 98304
#define QKVN_ (NROWS_*DH_)   // 6291456
#define DD_  (D_*D_)         // 589824
#define LOG2E_ 1.4426950408889634f

// Scratch (allocation-free: static __device__ globals)
__device__ __nv_bfloat16 g_xh[M_*D_],  g_xl[M_*D_];
__device__ __nv_bfloat16 g_wh[4*DD_],  g_wl[4*DD_];
__device__ __nv_bfloat16 g_qh[QKVN_],  g_ql[QKVN_];
__device__ __nv_bfloat16 g_kh[QKVN_],  g_kl[QKVN_];
__device__ __nv_bfloat16 g_vh[QKVN_],  g_vl[QKVN_];
__device__ __nv_bfloat16 g_ch[M_*D_],  g_cl[M_*D_];

// ===========================================================================
// Helpers
// ===========================================================================
__device__ __forceinline__ uint32_t smem_u32(const void* p) {
    uint32_t r;
    asm("{ .reg .u64 t; cvta.to.shared.u64 t, %1; cvt.u32.u64 %0, t; }"
        : "=r"(r) : "l"(p));
    return r;
}
__device__ __forceinline__ void ldsm_x4(uint32_t* r, uint32_t addr) {
    asm volatile("ldmatrix.sync.aligned.m8n8.x4.shared.b16 {%0,%1,%2,%3}, [%4];"
                 : "=r"(r[0]), "=r"(r[1]), "=r"(r[2]), "=r"(r[3]) : "r"(addr));
}
__device__ __forceinline__ void ldsm_x4_t(uint32_t* r, uint32_t addr) {
    asm volatile("ldmatrix.sync.aligned.m8n8.x4.trans.shared.b16 {%0,%1,%2,%3}, [%4];"
                 : "=r"(r[0]), "=r"(r[1]), "=r"(r[2]), "=r"(r[3]) : "r"(addr));
}
__device__ __forceinline__ void mma16816(float* d, const uint32_t* a,
                                         uint32_t b0, uint32_t b1) {
    asm volatile(
        "mma.sync.aligned.m16n8k16.row.col.f32.bf16.bf16.f32 "
        "{%0,%1,%2,%3}, {%4,%5,%6,%7}, {%8,%9}, {%0,%1,%2,%3};"
        : "+f"(d[0]), "+f"(d[1]), "+f"(d[2]), "+f"(d[3])
        : "r"(a[0]), "r"(a[1]), "r"(a[2]), "r"(a[3]), "r"(b0), "r"(b1));
}
// round-to-nearest hi/lo split (off the hot path)
__device__ __forceinline__ void split2(float x0, float x1, uint32_t& hi, uint32_t& lo) {
    __nv_bfloat16 h0 = __float2bfloat16_rn(x0);
    __nv_bfloat16 h1 = __float2bfloat16_rn(x1);
    __nv_bfloat16 l0 = __float2bfloat16_rn(x0 - __bfloat162float(h0));
    __nv_bfloat16 l1 = __float2bfloat16_rn(x1 - __bfloat162float(h1));
    hi = (uint32_t)__bfloat16_as_ushort(h0) | ((uint32_t)__bfloat16_as_ushort(h1) << 16);
    lo = (uint32_t)__bfloat16_as_ushort(l0) | ((uint32_t)__bfloat16_as_ushort(l1) << 16);
}
// cheap truncation split for softmax P (hot path)
__device__ __forceinline__ void psplit(float x0, float x1, uint32_t& hi, uint32_t& lo) {
    const uint32_t u0 = __float_as_uint(x0), u1 = __float_as_uint(x1);
    hi = __byte_perm(u0, u1, 0x7632);
    const float l0 = x0 - __uint_as_float(u0 & 0xFFFF0000u);
    const float l1 = x1 - __uint_as_float(u1 & 0xFFFF0000u);
    asm("cvt.rn.bf16x2.f32 %0, %1, %2;" : "=r"(lo) : "f"(l1), "f"(l0));
}
__device__ __forceinline__ float ex2(float x) {
    float y;
    asm("ex2.approx.f32 %0, %1;" : "=f"(y) : "f"(x));
    return y;
}
__device__ __forceinline__ void cp16(uint32_t dst, const void* src) {
    asm volatile("cp.async.cg.shared.global [%0], [%1], 16;" :: "r"(dst), "l"(src));
}
#define CP_COMMIT() asm volatile("cp.async.commit_group;" ::: "memory")
#define CP_WAIT(n)  asm volatile("cp.async.wait_group %0;" :: "n"(n) : "memory")

// ===========================================================================
// split kernels: fp32 -> bf16 hi/lo
// ===========================================================================
__global__ void __launch_bounds__(256)
xsplit_kernel(const float* __restrict__ src)
{
    const int i = (blockIdx.x * 256 + threadIdx.x) * 4;
    float4 v = *reinterpret_cast<const float4*>(src + i);
    uint32_t h0, l0, h1, l1;
    split2(v.x, v.y, h0, l0);
    split2(v.z, v.w, h1, l1);
    *reinterpret_cast<uint2*>(g_xh + i) = make_uint2(h0, h1);
    *reinterpret_cast<uint2*>(g_xl + i) = make_uint2(l0, l1);
}
__global__ void __launch_bounds__(256)
wsplit_kernel(const float* __restrict__ Wq, const float* __restrict__ Wk,
              const float* __restrict__ Wv, const float* __restrict__ Wo)
{
    const int per = DD_ / 1024;                   // 576
    const int wsel = blockIdx.x / per;
    const int bx   = blockIdx.x % per;
    const float* src = (wsel == 0) ? Wq : (wsel == 1) ? Wk : (wsel == 2) ? Wv : Wo;
    const int i = (bx * 256 + threadIdx.x) * 4;
    float4 v = *reinterpret_cast<const float4*>(src + i);
    uint32_t h0, l0, h1, l1;
    split2(v.x, v.y, h0, l0);
    split2(v.z, v.w, h1, l1);
    const size_t o = (size_t)wsel * DD_ + i;
    *reinterpret_cast<uint2*>(g_wh + o) = make_uint2(h0, h1);
    *reinterpret_cast<uint2*>(g_wl + o) = make_uint2(l0, l1);
}

// ===========================================================================
// GEMM mainloop (bf16 pre-split inputs): acc = A @ W^T, 128x128 tile
// ===========================================================================
#define LDK_  40
#define GARR  10240
#define GEMM_SMEM (8 * GARR)        // 80KB

__device__ __forceinline__ void gemm_body(
    const __nv_bfloat16* __restrict__ Ah, const __nv_bfloat16* __restrict__ Al,
    const __nv_bfloat16* __restrict__ Wh, const __nv_bfloat16* __restrict__ Wl,
    int m0, int n0, char* smem, float acc[4][4][4])
{
    const int tid    = threadIdx.x;
    const int lane   = tid & 31;
    const int wid    = tid >> 5;
    const int warp_m = wid & 1;
    const int warp_n = wid >> 1;
    const uint32_t sb = smem_u32(smem);

#pragma unroll
    for (int i = 0; i < 4; i++)
#pragma unroll
        for (int j = 0; j < 4; j++)
#pragma unroll
            for (int e = 0; e < 4; e++) acc[i][j][e] = 0.f;

    const int grow = tid >> 1;
    const int c16  = (tid & 1) * 2;
    const __nv_bfloat16* s0 = Ah + (size_t)(m0 + grow) * D_;
    const __nv_bfloat16* s1 = Al + (size_t)(m0 + grow) * D_;
    const __nv_bfloat16* s2 = Wh + (size_t)(n0 + grow) * D_;
    const __nv_bfloat16* s3 = Wl + (size_t)(n0 + grow) * D_;

    auto issue = [&](int kc, int bsel) {
        const uint32_t dst = sb + bsel * 4 * GARR + grow * 80 + c16 * 16;
#pragma unroll
        for (int j = 0; j < 2; j++) {
            cp16(dst + j * 16,            s0 + kc + (c16 + j) * 8);
            cp16(dst + j * 16 + GARR,     s1 + kc + (c16 + j) * 8);
            cp16(dst + j * 16 + 2 * GARR, s2 + kc + (c16 + j) * 8);
            cp16(dst + j * 16 + 3 * GARR, s3 + kc + (c16 + j) * 8);
        }
    };

    const int r_a = lane & 15, c_a = (lane >> 4) * 8;
    const int r_b = (lane & 7) | ((lane >> 4) << 3);
    const int c_b = ((lane >> 3) & 1) * 8;
    const uint32_t offA = ((warp_m * 64 + r_a) * LDK_ + c_a) * 2;
    const uint32_t offB = ((warp_n * 32 + r_b) * LDK_ + c_b) * 2;

    issue(0, 0);
    CP_COMMIT();

    const int NK = D_ / 32;   // 24
    for (int it = 0; it < NK; it++) {
        if (it + 1 < NK) {
            issue((it + 1) * 32, (it + 1) & 1);
            CP_COMMIT();
            CP_WAIT(1);
        } else {
            CP_WAIT(0);
        }
        __syncthreads();

        const uint32_t bAh = sb + ((it & 1) * 4 + 0) * GARR;
        const uint32_t bAl = bAh + GARR;
        const uint32_t bWh = bAh + 2 * GARR;
        const uint32_t bWl = bAh + 3 * GARR;

#pragma unroll
        for (int ks = 0; ks < 2; ks++) {
            const uint32_t ko = ks * 32;
            uint32_t ah[4][4], al[4][4];
#pragma unroll
            for (int mt = 0; mt < 4; mt++) {
                ldsm_x4(ah[mt], bAh + offA + ko + mt * 16 * LDK_ * 2);
                ldsm_x4(al[mt], bAl + offA + ko + mt * 16 * LDK_ * 2);
            }
            uint32_t bh[8], bl[8];
#pragma unroll
            for (int g = 0; g < 2; g++) {
                ldsm_x4(&bh[g * 4], bWh + offB + ko + g * 16 * LDK_ * 2);
                ldsm_x4(&bl[g * 4], bWl + offB + ko + g * 16 * LDK_ * 2);
            }
#pragma unroll
            for (int mt = 0; mt < 4; mt++)
#pragma unroll
                for (int nt = 0; nt < 4; nt++) {
                    mma16816(acc[mt][nt], ah[mt], bh[nt * 2], bh[nt * 2 + 1]);
                    mma16816(acc[mt][nt], ah[mt], bl[nt * 2], bl[nt * 2 + 1]);
                    mma16816(acc[mt][nt], al[mt], bh[nt * 2], bh[nt * 2 + 1]);
                }
        }
        __syncthreads();
    }
}

// ===========================================================================
// fused QKV GEMM: proj + bias + (L2 norm + scale for q,k) + bf16 split store.
// ===========================================================================
__global__ void __launch_bounds__(256, 2)
qkv_gemm(const float* __restrict__ bq, const float* __restrict__ bk,
         const float* __restrict__ bv, const float* __restrict__ ls)
{
    extern __shared__ char smem[];
    const int wsel = blockIdx.x / 6;
    const int n0   = (blockIdx.x % 6) * 128;
    const int m0   = blockIdx.y * 128;

    float acc[4][4][4];
    gemm_body(g_xh, g_xl, g_wh + (size_t)wsel * DD_, g_wl + (size_t)wsel * DD_,
              m0, n0, smem, acc);

    const int tid  = threadIdx.x;
    const int lane = tid & 31;
    const int wid  = tid >> 5;
    const int warp_m = wid & 1, warp_n = wid >> 1;

    const float* bias = (wsel == 0) ? bq : (wsel == 1) ? bk : bv;
    __nv_bfloat16* dh = (wsel == 0) ? g_qh : (wsel == 1) ? g_kh : g_vh;
    __nv_bfloat16* dl = (wsel == 0) ? g_ql : (wsel == 1) ? g_kl : g_vl;

    float2 bv2[4];
#pragma unroll
    for (int nt = 0; nt < 4; nt++)
        bv2[nt] = *reinterpret_cast<const float2*>(
            &bias[n0 + warp_n * 32 + nt * 8 + 2 * (lane & 3)]);
#pragma unroll
    for (int mt = 0; mt < 4; mt++)
#pragma unroll
        for (int nt = 0; nt < 4; nt++) {
            acc[mt][nt][0] += bv2[nt].x; acc[mt][nt][1] += bv2[nt].y;
            acc[mt][nt][2] += bv2[nt].x; acc[mt][nt][3] += bv2[nt].y;
        }

    __syncthreads();
    float* sq = reinterpret_cast<float*>(smem);   // [128][4]

    if (wsel < 2) {
#pragma unroll
        for (int mt = 0; mt < 4; mt++)
#pragma unroll
            for (int half = 0; half < 2; half++) {
                const int r = warp_m * 64 + mt * 16 + (lane >> 2) + half * 8;
                float p = 0.f;
#pragma unroll
                for (int nt = 0; nt < 4; nt++) {
                    const float a = acc[mt][nt][half * 2], bvv = acc[mt][nt][half * 2 + 1];
                    p += a * a + bvv * bvv;
                }
                p += __shfl_xor_sync(0xffffffffu, p, 1);
                p += __shfl_xor_sync(0xffffffffu, p, 2);
                if ((lane & 3) == 0) sq[r * 4 + warp_n] = p;
            }
        __syncthreads();
    }

    float scl = 1.f;
    if (wsel == 0) {
        const int hh = 2 * (blockIdx.x % 6) + (warp_n >> 1);
        scl = __expf(fminf(ls[hh], 4.6051701859880914f)) * LOG2E_;
    }

#pragma unroll
    for (int mt = 0; mt < 4; mt++) {
#pragma unroll
        for (int half = 0; half < 2; half++) {
            const int r = warp_m * 64 + mt * 16 + (lane >> 2) + half * 8;
            float inv = 1.f;
            if (wsel < 2) {
                const float s2 = sq[r * 4 + (warp_n & 2)] + sq[r * 4 + (warp_n & 2) + 1];
                inv = scl / fmaxf(sqrtf(s2), 1e-12f);
            }
            const int m  = m0 + r;
            const int bb = m >> 11, ss = m & (S_ - 1);
#pragma unroll
            for (int nt = 0; nt < 4; nt++) {
                const int n  = n0 + warp_n * 32 + nt * 8 + 2 * (lane & 3);
                const int hh = n >> 6, dd = n & 63;
                const size_t idx = (((size_t)(bb * H_ + hh)) * S_ + ss) * DH_ + dd;
                uint32_t hi, lo;
                split2(acc[mt][nt][half * 2] * inv, acc[mt][nt][half * 2 + 1] * inv, hi, lo);
                *reinterpret_cast<uint32_t*>(&dh[idx]) = hi;
                *reinterpret_cast<uint32_t*>(&dl[idx]) = lo;
            }
        }
    }
}

// output GEMM: ctx(split) @ Wo^T + bo -> d_out
__global__ void __launch_bounds__(256, 2)
o_gemm(const float* __restrict__ bo, float* __restrict__ out)
{
    extern __shared__ char smem[];
    const int n0 = blockIdx.x * 128;
    const int m0 = blockIdx.y * 128;

    float acc[4][4][4];
    gemm_body(g_ch, g_cl, g_wh + 3 * (size_t)DD_, g_wl + 3 * (size_t)DD_,
              m0, n0, smem, acc);

    const int lane = threadIdx.x & 31;
    const int wid  = threadIdx.x >> 5;
    const int warp_m = wid & 1, warp_n = wid >> 1;
#pragma unroll
    for (int mt = 0; mt < 4; mt++) {
#pragma unroll
        for (int nt = 0; nt < 4; nt++) {
            const int n = n0 + warp_n * 32 + nt * 8 + 2 * (lane & 3);
            const float2 bv2 = *reinterpret_cast<const float2*>(&bo[n]);
#pragma unroll
            for (int half = 0; half < 2; half++) {
                const int m = m0 + warp_m * 64 + mt * 16 + (lane >> 2) + half * 8;
                float2 o;
                o.x = acc[mt][nt][half * 2 + 0] + bv2.x;
                o.y = acc[mt][nt][half * 2 + 1] + bv2.y;
                *reinterpret_cast<float2*>(out + (size_t)m * D_ + n) = o;
            }
        }
    }
}

// ===========================================================================
// HMMA flash attention (bf16x3) with FIXED-MAX softmax.
// Scores bounded: s = scale*log2e*cos <= M := scale*log2e (q pre-scaled).
// p = exp2(s - M) -- no online max, no rescale, no in-loop shfls.
// ===========================================================================
#define ABUF   9216
#define ATTN_SMEM (12 * ABUF)      // 3 buffers x {Kh,Kl,Vh,Vl}

__global__ void __launch_bounds__(256, 2)
attn_mma(const float* __restrict__ ls)
{
    extern __shared__ char sm[];
    const uint32_t sbase = smem_u32(sm);
    const int tid  = threadIdx.x;
    const int lane = tid & 31;
    const int wid  = tid >> 5;
    const int bh   = blockIdx.y;
    const int h    = bh % H_;
    const int b    = bh / H_;
    const int q0   = blockIdx.x * 128;
    const size_t base = (size_t)bh * S_ * DH_;
    const float Mfix = __expf(fminf(ls[h], 4.6051701859880914f)) * LOG2E_;

    // stage Q hi/lo into smem, build A-fragments, release
    {
        const __nv_bfloat16* gq0 = g_qh + base + (size_t)q0 * DH_;
        const __nv_bfloat16* gq1 = g_ql + base + (size_t)q0 * DH_;
#pragma unroll
        for (int i = 0; i < 8; i++) {
            const int arr = i >> 2;
            const int idx = ((i & 3) << 8) + tid;
            const int row = idx >> 3, c = idx & 7;
            const uint4 v = *reinterpret_cast<const uint4*>(
                (arr ? gq1 : gq0) + row * DH_ + c * 8);
            *reinterpret_cast<uint4*>(sm + arr * 18432 + row * 144 + c * 16) = v;
        }
    }
    __syncthreads();
    uint32_t qfh[4][4], qfl[4][4];
    {
        const uint32_t qa = sbase + (wid * 16 + (lane & 15)) * 144 + (lane >> 4) * 16;
#pragma unroll
        for (int kt = 0; kt < 4; kt++) {
            ldsm_x4(qfh[kt], qa + kt * 32);
            ldsm_x4(qfl[kt], qa + 18432 + kt * 32);
        }
    }
    __syncthreads();

    float o[8][4];
#pragma unroll
    for (int nt = 0; nt < 8; nt++)
#pragma unroll
        for (int e = 0; e < 4; e++) o[nt][e] = 0.f;
    float l0 = 0.f, l1 = 0.f;

    const uint32_t lofs = (lane & 15) * 144 + (lane >> 4) * 16;

    const __nv_bfloat16* gkh = g_kh + base;
    const __nv_bfloat16* gkl = g_kl + base;
    const __nv_bfloat16* gvh = g_vh + base;
    const __nv_bfloat16* gvl = g_vl + base;

    auto issue = [&](int it, int bsel) {
        const int koff = it * 64 * DH_;
#pragma unroll
        for (int i = 0; i < 8; i++) {
            const int arr = i >> 1;
            const int idx = ((i & 1) << 8) + tid;
            const int row = idx >> 3, c = idx & 7;
            const __nv_bfloat16* gp =
                (arr == 0 ? gkh : arr == 1 ? gkl : arr == 2 ? gvh : gvl)
                + koff + row * DH_ + c * 8;
            cp16(sbase + (bsel * 4 + arr) * ABUF + row * 144 + c * 16, gp);
        }
    };

    issue(0, 0); CP_COMMIT();
    issue(1, 1); CP_COMMIT();

    const int NIT = S_ / 64;   // 32
    for (int it = 0; it < NIT; it++) {
        if (it + 1 < NIT) { CP_WAIT(1); } else { CP_WAIT(0); }
        __syncthreads();
        if (it + 2 < NIT) { issue(it + 2, (it + 2) % 3); CP_COMMIT(); }

        const uint32_t Kh = sbase + ((it % 3) * 4) * ABUF;
        const uint32_t Kl = Kh + ABUF;
        const uint32_t Vh = Kh + 2 * ABUF;
        const uint32_t Vl = Kh + 3 * ABUF;

        // ---- S - M = Q' @ K^T - M  (accumulator initialized to -M)
        float s[8][4];
#pragma unroll
        for (int nt = 0; nt < 8; nt++)
#pragma unroll
            for (int e = 0; e < 4; e++) s[nt][e] = -Mfix;

#pragma unroll
        for (int kt = 0; kt < 4; kt++) {
#pragma unroll
            for (int g = 0; g < 4; g++) {
                uint32_t kf[4], lf[4];
                ldsm_x4(kf, Kh + lofs + g * 16 * 144 + kt * 32);
                ldsm_x4(lf, Kl + lofs + g * 16 * 144 + kt * 32);
                mma16816(s[2 * g],     qfh[kt], kf[0], kf[2]);
                mma16816(s[2 * g],     qfh[kt], lf[0], lf[2]);
                mma16816(s[2 * g],     qfl[kt], kf[0], kf[2]);
                mma16816(s[2 * g + 1], qfh[kt], kf[1], kf[3]);
                mma16816(s[2 * g + 1], qfh[kt], lf[1], lf[3]);
                mma16816(s[2 * g + 1], qfl[kt], kf[1], kf[3]);
            }
        }

        // ---- p = exp2(s - M); accumulate l locally (no shfls)
#pragma unroll
        for (int nt = 0; nt < 8; nt++) {
            s[nt][0] = ex2(s[nt][0]);
            s[nt][1] = ex2(s[nt][1]);
            s[nt][2] = ex2(s[nt][2]);
            s[nt][3] = ex2(s[nt][3]);
            l0 += s[nt][0] + s[nt][1];
            l1 += s[nt][2] + s[nt][3];
        }

        // ---- O += P @ V  (truncation split for P)
#pragma unroll
        for (int kt = 0; kt < 4; kt++) {
            uint32_t ah[4], al[4];
            psplit(s[2 * kt][0],     s[2 * kt][1],     ah[0], al[0]);
            psplit(s[2 * kt][2],     s[2 * kt][3],     ah[1], al[1]);
            psplit(s[2 * kt + 1][0], s[2 * kt + 1][1], ah[2], al[2]);
            psplit(s[2 * kt + 1][2], s[2 * kt + 1][3], ah[3], al[3]);
#pragma unroll
            for (int g = 0; g < 4; g++) {
                uint32_t vf[4], wf[4];
                ldsm_x4_t(vf, Vh + lofs + kt * 16 * 144 + g * 32);
                ldsm_x4_t(wf, Vl + lofs + kt * 16 * 144 + g * 32);
                mma16816(o[2 * g],     ah, vf[0], vf[1]);
                mma16816(o[2 * g],     ah, wf[0], wf[1]);
                mma16816(o[2 * g],     al, vf[0], vf[1]);
                mma16816(o[2 * g + 1], ah, vf[2], vf[3]);
                mma16816(o[2 * g + 1], ah, wf[2], wf[3]);
                mma16816(o[2 * g + 1], al, vf[2], vf[3]);
            }
        }
    }

    // epilogue: reduce l across quad lanes once, normalize, store bf16 splits
    l0 += __shfl_xor_sync(0xffffffffu, l0, 1);
    l0 += __shfl_xor_sync(0xffffffffu, l0, 2);
    l1 += __shfl_xor_sync(0xffffffffu, l1, 1);
    l1 += __shfl_xor_sync(0xffffffffu, l1, 2);
    const float inv0 = 1.f / l0;
    const float inv1 = 1.f / l1;
    const int row0 = q0 + wid * 16 + (lane >> 2);
    const int col0 = h * DH_ + 2 * (lane & 3);
    const size_t p0 = ((size_t)b * S_ + row0) * D_ + col0;
    const size_t p1 = p0 + 8 * D_;
#pragma unroll
    for (int nt = 0; nt < 8; nt++) {
        uint32_t hi, lo;
        split2(o[nt][0] * inv0, o[nt][1] * inv0, hi, lo);
        *reinterpret_cast<uint32_t*>(g_ch + p0 + nt * 8) = hi;
        *reinterpret_cast<uint32_t*>(g_cl + p0 + nt * 8) = lo;
        split2(o[nt][2] * inv1, o[nt][3] * inv1, hi, lo);
        *reinterpret_cast<uint32_t*>(g_ch + p1 + nt * 8) = hi;
        *reinterpret_cast<uint32_t*>(g_cl + p1 + nt * 8) = lo;
    }
}

// ---------------------------------------------------------------------------
// Launch
// ---------------------------------------------------------------------------
extern "C" void kernel_launch(void* const* d_in, const int* in_sizes, int n_in,
                              void* d_out, int out_size)
{
    const float* x  = (const float*)d_in[0];
    const float* Wq = (const float*)d_in[1];
    const float* bq = (const float*)d_in[2];
    const float* Wk = (const float*)d_in[3];
    const float* bk = (const float*)d_in[4];
    const float* Wv = (const float*)d_in[5];
    const float* bv = (const float*)d_in[6];
    const float* Wo = (const float*)d_in[7];
    const float* bo = (const float*)d_in[8];
    const float* ls = (const float*)d_in[9];
    float* out = (float*)d_out;

    xsplit_kernel<<<(M_ * D_) / 1024, 256>>>(x);
    wsplit_kernel<<<4 * (DD_ / 1024), 256>>>(Wq, Wk, Wv, Wo);

    cudaFuncSetAttribute(qkv_gemm, cudaFuncAttributeMaxDynamicSharedMemorySize, GEMM_SMEM);
    cudaFuncSetAttribute(o_gemm,   cudaFuncAttributeMaxDynamicSharedMemorySize, GEMM_SMEM);
    cudaFuncSetAttribute(attn_mma, cudaFuncAttributeMaxDynamicSharedMemorySize, ATTN_SMEM);

    qkv_gemm<<<dim3(18, M_ / 128), 256, GEMM_SMEM>>>(bq, bk, bv, ls);

    attn_mma<<<dim3(S_ / 128, B_ * H_), 256, ATTN_SMEM>>>(ls);

    o_gemm<<<dim3(D_ / 128, M_ / 128), 256, GEMM_SMEM>>>(bo, out);
}